// round 1
// baseline (speedup 1.0000x reference)
#include <cuda_runtime.h>
#include <math.h>
#include <float.h>

// Problem constants (fixed by dataset)
#define NN 50000
#define HH 64
#define EE 250000
#define PP 3
#define HEADS 4
#define DD 256
#define FHH 128

// ---------------- scratch (static device memory; no allocs) ----------------
__device__ float g_fr[2][3][32][2];        // rotation factors per path/pos/complex
__device__ float g_a1n[NN * 4];            // per-node celu3(features @ attn1_w^T)
__device__ float g_eft[(size_t)EE * 64];   // per-edge features (reused per path)
__device__ float g_a[(size_t)EE * 4];      // per-edge attention logits
__device__ int   g_counts[NN];
__device__ int   g_offsets[NN];
__device__ int   g_cursor[NN];
__device__ int   g_part[64];
__device__ int   g_order[EE];
__device__ float g_z[(size_t)NN * 512];    // (N, 2 paths, 256)
__device__ float g_w[2];
__device__ float g_beta[2];

// ---------------- helpers ----------------
__device__ __forceinline__ float celu3f(float x) {
    return x > 0.f ? x : 3.f * expm1f(x * (1.f / 3.f));
}
__device__ __forceinline__ float sigmf(float x) {
    return 1.f / (1.f + expf(-x));
}
__device__ __forceinline__ float wredsum(float v) {
#pragma unroll
    for (int o = 16; o; o >>= 1) v += __shfl_xor_sync(0xffffffffu, v, o);
    return v;
}
__device__ __forceinline__ float wredmax(float v) {
#pragma unroll
    for (int o = 16; o; o >>= 1) v = fmaxf(v, __shfl_xor_sync(0xffffffffu, v, o));
    return v;
}

// ---------------- kernels ----------------

// Compute rotation factors fr[m][p][c] and zero w accumulators.
__global__ void init_kernel(const float* __restrict__ r_vec) {
    int t = threadIdx.x;
    if (t < 2) g_w[t] = 0.f;
    if (t < 32) {
        float nre[4], nim[4];
#pragma unroll
        for (int r = 0; r < 4; r++) {
            float re = r_vec[r * 64 + t * 2];
            float im = r_vec[r * 64 + t * 2 + 1];
            float inv = 1.f / sqrtf(re * re + im * im);
            nre[r] = re * inv;
            nim[r] = im * inv;
        }
#pragma unroll
        for (int m = 0; m < 2; m++) {
            int a = 2 * m + 1, b = 2 * m;
            // p=2: identity
            g_fr[m][2][t][0] = 1.f; g_fr[m][2][t][1] = 0.f;
            // p=1: rv[2m+1]
            g_fr[m][1][t][0] = nre[a]; g_fr[m][1][t][1] = nim[a];
            // p=0: rv[2m+1] * rv[2m]
            g_fr[m][0][t][0] = nre[a] * nre[b] - nim[a] * nim[b];
            g_fr[m][0][t][1] = nre[a] * nim[b] + nim[a] * nre[b];
        }
    }
}

// Per-node a1 = celu3(features @ attn1_w^T). One warp per node.
__global__ void a1n_kernel(const float* __restrict__ feat, const float* __restrict__ aw) {
    int gw = (blockIdx.x * blockDim.x + threadIdx.x) >> 5;
    int lane = threadIdx.x & 31;
    if (gw >= NN) return;
    float2 d = reinterpret_cast<const float2*>(feat)[gw * 32 + lane];
    float p[4];
#pragma unroll
    for (int h = 0; h < 4; h++) {
        float v = aw[h * 64 + 2 * lane] * d.x + aw[h * 64 + 2 * lane + 1] * d.y;
        p[h] = wredsum(v);
    }
    if (lane == 0) {
        float4 r;
        r.x = celu3f(p[0]); r.y = celu3f(p[1]); r.z = celu3f(p[2]); r.w = celu3f(p[3]);
        reinterpret_cast<float4*>(g_a1n)[gw] = r;
    }
}

// Per-edge: gather 3 feature rows, rotate, mean, gate -> eft; logits -> a; histogram counts.
__global__ void edge_kernel(const float* __restrict__ feat, const int* __restrict__ inst,
                            const float* __restrict__ attn2, int m) {
    int gw = (blockIdx.x * blockDim.x + threadIdx.x) >> 5;
    int lane = threadIdx.x & 31;
    if (gw >= EE) return;
    int e = gw;
    const int* ip = inst + (size_t)m * EE * 3 + (size_t)e * 3;
    int n0 = ip[0];
    float mre = 0.f, mim = 0.f;
#pragma unroll
    for (int p = 0; p < 3; p++) {
        int np = ip[p];
        float2 d = reinterpret_cast<const float2*>(feat)[np * 32 + lane];
        float fre = g_fr[m][p][lane][0];
        float fim = g_fr[m][p][lane][1];
        mre += d.x * fre - d.y * fim;
        mim += d.x * fim + d.y * fre;
    }
    mre *= (1.f / 3.f); mim *= (1.f / 3.f);
    float sx = celu3f(mre) * sigmf(mre);
    float sy = celu3f(mim) * sigmf(mim);
    float ex_ = celu3f(sx);
    float ey_ = celu3f(sy);
    reinterpret_cast<float2*>(g_eft)[(size_t)e * 32 + lane] = make_float2(ex_, ey_);
    float a2[4];
#pragma unroll
    for (int h = 0; h < 4; h++) {
        float v = attn2[h * 64 + 2 * lane] * ex_ + attn2[h * 64 + 2 * lane + 1] * ey_;
        a2[h] = wredsum(v);
    }
    if (lane == 0) {
        float4 av;
        av.x = celu3f(g_a1n[n0 * 4 + 0] + a2[0]);
        av.y = celu3f(g_a1n[n0 * 4 + 1] + a2[1]);
        av.z = celu3f(g_a1n[n0 * 4 + 2] + a2[2]);
        av.w = celu3f(g_a1n[n0 * 4 + 3] + a2[3]);
        reinterpret_cast<float4*>(g_a)[e] = av;
        atomicAdd(&g_counts[n0], 1);
    }
}

// Hierarchical exclusive scan of counts -> offsets (+ cursor copy).
__global__ void scan1_kernel() {
    __shared__ int s[1024];
    int t = threadIdx.x;
    int i = blockIdx.x * 1024 + t;
    int v = (i < NN) ? g_counts[i] : 0;
    s[t] = v;
    __syncthreads();
    for (int off = 1; off < 1024; off <<= 1) {
        int x = (t >= off) ? s[t - off] : 0;
        __syncthreads();
        s[t] += x;
        __syncthreads();
    }
    if (i < NN) g_offsets[i] = s[t] - v;
    if (t == 1023) g_part[blockIdx.x] = s[1023];
}
__global__ void scan2_kernel(int nblk) {
    int run = 0;
    for (int b = 0; b < nblk; b++) { int x = g_part[b]; g_part[b] = run; run += x; }
}
__global__ void scan3_kernel() {
    int i = blockIdx.x * 1024 + threadIdx.x;
    if (i < NN) {
        int o = g_offsets[i] + g_part[blockIdx.x];
        g_offsets[i] = o;
        g_cursor[i] = o;
    }
}

__global__ void scatter_kernel(const int* __restrict__ inst, int m) {
    int e = blockIdx.x * blockDim.x + threadIdx.x;
    if (e >= EE) return;
    int seg = inst[(size_t)m * EE * 3 + (size_t)e * 3];
    int pos = atomicAdd(&g_cursor[seg], 1);
    g_order[pos] = e;
}

// One warp per node: segment softmax + weighted sum of eft -> z (no global atomics).
__global__ void node_kernel(int m) {
    int gw = (blockIdx.x * blockDim.x + threadIdx.x) >> 5;
    int lane = threadIdx.x & 31;
    if (gw >= NN) return;
    int n = gw;
    int deg = g_counts[n];
    int start = g_offsets[n];
    float mx[4] = {-FLT_MAX, -FLT_MAX, -FLT_MAX, -FLT_MAX};
    for (int i = lane; i < deg; i += 32) {
        int e = g_order[start + i];
        float4 a = reinterpret_cast<const float4*>(g_a)[e];
        mx[0] = fmaxf(mx[0], a.x); mx[1] = fmaxf(mx[1], a.y);
        mx[2] = fmaxf(mx[2], a.z); mx[3] = fmaxf(mx[3], a.w);
    }
#pragma unroll
    for (int h = 0; h < 4; h++) mx[h] = wredmax(mx[h]);
    float sm4[4] = {0.f, 0.f, 0.f, 0.f};
    for (int i = lane; i < deg; i += 32) {
        int e = g_order[start + i];
        float4 a = reinterpret_cast<const float4*>(g_a)[e];
        sm4[0] += expf(a.x - mx[0]); sm4[1] += expf(a.y - mx[1]);
        sm4[2] += expf(a.z - mx[2]); sm4[3] += expf(a.w - mx[3]);
    }
    float inv[4];
#pragma unroll
    for (int h = 0; h < 4; h++) {
        sm4[h] = wredsum(sm4[h]);
        inv[h] = (deg > 0) ? (1.f / sm4[h]) : 0.f;
    }
    float acc[8];
#pragma unroll
    for (int t = 0; t < 8; t++) acc[t] = 0.f;
    for (int i = 0; i < deg; i++) {
        int e = g_order[start + i];
        float4 a = reinterpret_cast<const float4*>(g_a)[e];
        float wv[4];
        wv[0] = expf(a.x - mx[0]) * inv[0];
        wv[1] = expf(a.y - mx[1]) * inv[1];
        wv[2] = expf(a.z - mx[2]) * inv[2];
        wv[3] = expf(a.w - mx[3]) * inv[3];
        const float* er = g_eft + (size_t)e * 64;
#pragma unroll
        for (int t = 0; t < 8; t++) {
            int k = lane + 32 * (t & 1);
            acc[t] += wv[t >> 1] * er[k];
        }
    }
    float* zr = g_z + (size_t)n * 512 + m * 256;
#pragma unroll
    for (int t = 0; t < 8; t++) zr[lane + 32 * t] = celu3f(acc[t]);
}

// MLP: 32 rows/block, thread = output column. Accumulates sum of fw3*t2 into g_w.
__global__ __launch_bounds__(256) void mlp_kernel(
    const float* __restrict__ fw1, const float* __restrict__ fb1,
    const float* __restrict__ fw2, const float* __restrict__ fb2,
    const float* __restrict__ fw3) {
    extern __shared__ float smem[];
    float* zs  = smem;           // 32*256
    float* t1s = smem + 8192;    // 32*256
    float* ws  = smem + 16384;   // 256*33
    int tid = threadIdx.x;
    size_t base = (size_t)blockIdx.x * 32 * 256;

    for (int i = tid; i < 8192; i += 256) zs[i] = g_z[base + i];

    float acc[32];
#pragma unroll
    for (int r = 0; r < 32; r++) acc[r] = 0.f;

    for (int kc = 0; kc < 256; kc += 32) {
        __syncthreads();
        for (int i = tid; i < 8192; i += 256) {
            int o = i >> 5, j = i & 31;
            ws[o * 33 + j] = fw1[o * 256 + kc + j];
        }
        __syncthreads();
#pragma unroll 4
        for (int j = 0; j < 32; j++) {
            float wv = ws[tid * 33 + j];
            const float* zc = zs + kc + j;
#pragma unroll
            for (int r = 0; r < 32; r++) acc[r] += wv * zc[r * 256];
        }
    }
    __syncthreads();
    {
        float b = fb1[tid];
#pragma unroll
        for (int r = 0; r < 32; r++) t1s[r * 256 + tid] = celu3f(acc[r] + b);
    }

    int o2 = tid & 127;
    int rh = tid >> 7;
    float acc2[16];
#pragma unroll
    for (int r = 0; r < 16; r++) acc2[r] = 0.f;

    for (int kc = 0; kc < 256; kc += 32) {
        __syncthreads();
        for (int i = tid; i < 4096; i += 256) {
            int o = i >> 5, j = i & 31;
            ws[o * 33 + j] = fw2[o * 256 + kc + j];
        }
        __syncthreads();
#pragma unroll 4
        for (int j = 0; j < 32; j++) {
            float wv = ws[o2 * 33 + j];
            const float* tc = t1s + (rh * 16) * 256 + kc + j;
#pragma unroll
            for (int r = 0; r < 16; r++) acc2[r] += wv * tc[r * 256];
        }
    }

    float b2 = fb2[o2], w3 = fw3[o2];
    float loc0 = 0.f, loc1 = 0.f;
#pragma unroll
    for (int r = 0; r < 16; r++) {
        float t2 = celu3f(acc2[r] + b2);
        if (r & 1) loc1 += t2 * w3; else loc0 += t2 * w3;
    }
#pragma unroll
    for (int o = 16; o; o >>= 1) {
        loc0 += __shfl_xor_sync(0xffffffffu, loc0, o);
        loc1 += __shfl_xor_sync(0xffffffffu, loc1, o);
    }
    __shared__ float red[8][2];
    int wid = tid >> 5;
    if ((tid & 31) == 0) { red[wid][0] = loc0; red[wid][1] = loc1; }
    __syncthreads();
    if (tid == 0) {
        float s0 = 0.f, s1 = 0.f;
#pragma unroll
        for (int w = 0; w < 8; w++) { s0 += red[w][0]; s1 += red[w][1]; }
        atomicAdd(&g_w[0], s0);
        atomicAdd(&g_w[1], s1);
    }
}

__global__ void beta_kernel() {
    float w0 = g_w[0] * (1.f / (float)NN);
    float w1 = g_w[1] * (1.f / (float)NN);
    float mx = fmaxf(w0, w1);
    float e0 = expf(w0 - mx), e1 = expf(w1 - mx);
    float inv = 1.f / (e0 + e1);
    g_beta[0] = e0 * inv;
    g_beta[1] = e1 * inv;
}

__global__ void final_kernel(float* __restrict__ out) {
    int idx = blockIdx.x * blockDim.x + threadIdx.x; // over N*64 float4s
    if (idx >= NN * 64) return;
    int n = idx >> 6;
    int q = idx & 63;
    float4 z0 = reinterpret_cast<const float4*>(g_z)[(size_t)n * 128 + q];
    float4 z1 = reinterpret_cast<const float4*>(g_z)[(size_t)n * 128 + 64 + q];
    float b0 = g_beta[0], b1 = g_beta[1];
    float4 o;
    o.x = b0 * z0.x + b1 * z1.x;
    o.y = b0 * z0.y + b1 * z1.y;
    o.z = b0 * z0.z + b1 * z1.z;
    o.w = b0 * z0.w + b1 * z1.w;
    reinterpret_cast<float4*>(out)[idx] = o;
}

// ---------------- launch ----------------
extern "C" void kernel_launch(void* const* d_in, const int* in_sizes, int n_in,
                              void* d_out, int out_size) {
    const float* feat    = (const float*)d_in[0];
    const float* r_vec   = (const float*)d_in[1];
    const float* attn1_w = (const float*)d_in[2];
    const float* attn2   = (const float*)d_in[3];
    const float* fw1     = (const float*)d_in[4];
    const float* fb1     = (const float*)d_in[5];
    const float* fw2     = (const float*)d_in[6];
    const float* fb2     = (const float*)d_in[7];
    const float* fw3     = (const float*)d_in[8];
    const int*   inst    = (const int*)d_in[9];
    float* out = (float*)d_out;

    void* cptr = nullptr;
    cudaGetSymbolAddress(&cptr, g_counts);

    const int SCAN_BLOCKS = (NN + 1023) / 1024; // 49

    init_kernel<<<1, 64>>>(r_vec);
    a1n_kernel<<<(NN * 32 + 255) / 256, 256>>>(feat, attn1_w);

    for (int m = 0; m < 2; m++) {
        cudaMemsetAsync(cptr, 0, NN * sizeof(int));
        edge_kernel<<<(EE * 32 + 255) / 256, 256>>>(feat, inst, attn2, m);
        scan1_kernel<<<SCAN_BLOCKS, 1024>>>();
        scan2_kernel<<<1, 1>>>(SCAN_BLOCKS);
        scan3_kernel<<<SCAN_BLOCKS, 1024>>>();
        scatter_kernel<<<(EE + 255) / 256, 256>>>(inst, m);
        node_kernel<<<(NN * 32 + 255) / 256, 256>>>(m);
    }

    int smemB = (8192 + 8192 + 256 * 33) * 4;
    cudaFuncSetAttribute(mlp_kernel, cudaFuncAttributeMaxDynamicSharedMemorySize, smemB);
    mlp_kernel<<<(NN * 2) / 32, 256, smemB>>>(fw1, fb1, fw2, fb2, fw3);
    beta_kernel<<<1, 1>>>();
    final_kernel<<<(NN * 64 + 255) / 256, 256>>>(out);
}

// round 6
// speedup vs baseline: 2.4190x; 2.4190x over previous
#include <cuda_runtime.h>
#include <cuda_bf16.h>
#include <math.h>
#include <float.h>
#include <stdint.h>

// Problem constants (fixed by dataset)
#define NN 50000
#define HH 64
#define EE 250000
#define HEADS 4
#define ROWS_TOT (NN * 2)          // 100000 MLP rows (N nodes x 2 paths)
#define MLP_CTAS ((ROWS_TOT + 127) / 128)

// ---------------- scratch (static device memory; no allocs) ----------------
__device__ float g_fr[2][3][32][2];
__device__ float g_a1n[NN * 4];
__device__ float g_eft[(size_t)EE * 64];
__device__ float g_a[(size_t)EE * 4];
__device__ int   g_counts[NN];
__device__ int   g_offsets[NN];
__device__ int   g_cursor[NN];
__device__ int   g_part[64];
__device__ int   g_order[EE];
__device__ float g_z[(size_t)NN * 512];                       // fp32 (N, 2, 256)
__device__ __align__(16) __nv_bfloat16 g_zb[(size_t)ROWS_TOT * 256]; // bf16 rows
__device__ __align__(16) __nv_bfloat16 g_fw1b[256 * 256];
__device__ __align__(16) __nv_bfloat16 g_fw2b[128 * 256];
__device__ float g_w[2];
__device__ float g_beta[2];

// ---------------- helpers ----------------
__device__ __forceinline__ float celu3f(float x) {
    return x > 0.f ? x : 3.f * expm1f(x * (1.f / 3.f));
}
__device__ __forceinline__ float sigmf(float x) {
    return 1.f / (1.f + expf(-x));
}
__device__ __forceinline__ float wredsum(float v) {
#pragma unroll
    for (int o = 16; o; o >>= 1) v += __shfl_xor_sync(0xffffffffu, v, o);
    return v;
}
__device__ __forceinline__ float wredmax(float v) {
#pragma unroll
    for (int o = 16; o; o >>= 1) v = fmaxf(v, __shfl_xor_sync(0xffffffffu, v, o));
    return v;
}
__device__ __forceinline__ uint32_t smem_to_u32(const void* p) {
    uint32_t a;
    asm("{ .reg .u64 t; cvta.to.shared.u64 t, %1; cvt.u32.u64 %0, t; }" : "=r"(a) : "l"(p));
    return a;
}

// ldmatrix x4 (four 8x8 b16 tiles)
__device__ __forceinline__ void ldsm_x4(uint32_t addr, uint32_t* r) {
    asm volatile("ldmatrix.sync.aligned.m8n8.x4.shared.b16 {%0,%1,%2,%3}, [%4];"
                 : "=r"(r[0]), "=r"(r[1]), "=r"(r[2]), "=r"(r[3]) : "r"(addr));
}
// mma m16n8k16 bf16 -> f32 accum (in place)
__device__ __forceinline__ void mma_bf16(float* d, const uint32_t* a, const uint32_t* b) {
    asm volatile(
        "mma.sync.aligned.m16n8k16.row.col.f32.bf16.bf16.f32 "
        "{%0,%1,%2,%3}, {%4,%5,%6,%7}, {%8,%9}, {%0,%1,%2,%3};"
        : "+f"(d[0]), "+f"(d[1]), "+f"(d[2]), "+f"(d[3])
        : "r"(a[0]), "r"(a[1]), "r"(a[2]), "r"(a[3]), "r"(b[0]), "r"(b[1]));
}

// ---------------- kernels ----------------

__global__ void init_kernel(const float* __restrict__ r_vec) {
    int t = threadIdx.x;
    if (t < 2) g_w[t] = 0.f;
    if (t < 32) {
        float nre[4], nim[4];
#pragma unroll
        for (int r = 0; r < 4; r++) {
            float re = r_vec[r * 64 + t * 2];
            float im = r_vec[r * 64 + t * 2 + 1];
            float inv = 1.f / sqrtf(re * re + im * im);
            nre[r] = re * inv;
            nim[r] = im * inv;
        }
#pragma unroll
        for (int m = 0; m < 2; m++) {
            int a = 2 * m + 1, b = 2 * m;
            g_fr[m][2][t][0] = 1.f; g_fr[m][2][t][1] = 0.f;
            g_fr[m][1][t][0] = nre[a]; g_fr[m][1][t][1] = nim[a];
            g_fr[m][0][t][0] = nre[a] * nre[b] - nim[a] * nim[b];
            g_fr[m][0][t][1] = nre[a] * nim[b] + nim[a] * nre[b];
        }
    }
}

__global__ void wconv_kernel(const float* __restrict__ fw1, const float* __restrict__ fw2) {
    int i = blockIdx.x * blockDim.x + threadIdx.x;
    if (i < 256 * 256) g_fw1b[i] = __float2bfloat16(fw1[i]);
    if (i < 128 * 256) g_fw2b[i] = __float2bfloat16(fw2[i]);
}

__global__ void a1n_kernel(const float* __restrict__ feat, const float* __restrict__ aw) {
    int gw = (blockIdx.x * blockDim.x + threadIdx.x) >> 5;
    int lane = threadIdx.x & 31;
    if (gw >= NN) return;
    float2 d = reinterpret_cast<const float2*>(feat)[gw * 32 + lane];
    float p[4];
#pragma unroll
    for (int h = 0; h < 4; h++) {
        float v = aw[h * 64 + 2 * lane] * d.x + aw[h * 64 + 2 * lane + 1] * d.y;
        p[h] = wredsum(v);
    }
    if (lane == 0) {
        float4 r;
        r.x = celu3f(p[0]); r.y = celu3f(p[1]); r.z = celu3f(p[2]); r.w = celu3f(p[3]);
        reinterpret_cast<float4*>(g_a1n)[gw] = r;
    }
}

__global__ void edge_kernel(const float* __restrict__ feat, const int* __restrict__ inst,
                            const float* __restrict__ attn2, int m) {
    int gw = (blockIdx.x * blockDim.x + threadIdx.x) >> 5;
    int lane = threadIdx.x & 31;
    if (gw >= EE) return;
    int e = gw;
    const int* ip = inst + (size_t)m * EE * 3 + (size_t)e * 3;
    int n0 = ip[0];
    float mre = 0.f, mim = 0.f;
#pragma unroll
    for (int p = 0; p < 3; p++) {
        int np = ip[p];
        float2 d = reinterpret_cast<const float2*>(feat)[np * 32 + lane];
        float fre = g_fr[m][p][lane][0];
        float fim = g_fr[m][p][lane][1];
        mre += d.x * fre - d.y * fim;
        mim += d.x * fim + d.y * fre;
    }
    mre *= (1.f / 3.f); mim *= (1.f / 3.f);
    float sx = celu3f(mre) * sigmf(mre);
    float sy = celu3f(mim) * sigmf(mim);
    float ex_ = celu3f(sx);
    float ey_ = celu3f(sy);
    reinterpret_cast<float2*>(g_eft)[(size_t)e * 32 + lane] = make_float2(ex_, ey_);
    float a2[4];
#pragma unroll
    for (int h = 0; h < 4; h++) {
        float v = attn2[h * 64 + 2 * lane] * ex_ + attn2[h * 64 + 2 * lane + 1] * ey_;
        a2[h] = wredsum(v);
    }
    if (lane == 0) {
        float4 av;
        av.x = celu3f(g_a1n[n0 * 4 + 0] + a2[0]);
        av.y = celu3f(g_a1n[n0 * 4 + 1] + a2[1]);
        av.z = celu3f(g_a1n[n0 * 4 + 2] + a2[2]);
        av.w = celu3f(g_a1n[n0 * 4 + 3] + a2[3]);
        reinterpret_cast<float4*>(g_a)[e] = av;
        atomicAdd(&g_counts[n0], 1);
    }
}

__global__ void scan1_kernel() {
    __shared__ int s[1024];
    int t = threadIdx.x;
    int i = blockIdx.x * 1024 + t;
    int v = (i < NN) ? g_counts[i] : 0;
    s[t] = v;
    __syncthreads();
    for (int off = 1; off < 1024; off <<= 1) {
        int x = (t >= off) ? s[t - off] : 0;
        __syncthreads();
        s[t] += x;
        __syncthreads();
    }
    if (i < NN) g_offsets[i] = s[t] - v;
    if (t == 1023) g_part[blockIdx.x] = s[1023];
}
__global__ void scan2_kernel(int nblk) {
    int run = 0;
    for (int b = 0; b < nblk; b++) { int x = g_part[b]; g_part[b] = run; run += x; }
}
__global__ void scan3_kernel() {
    int i = blockIdx.x * 1024 + threadIdx.x;
    if (i < NN) {
        int o = g_offsets[i] + g_part[blockIdx.x];
        g_offsets[i] = o;
        g_cursor[i] = o;
    }
}

__global__ void scatter_kernel(const int* __restrict__ inst, int m) {
    int e = blockIdx.x * blockDim.x + threadIdx.x;
    if (e >= EE) return;
    int seg = inst[(size_t)m * EE * 3 + (size_t)e * 3];
    int pos = atomicAdd(&g_cursor[seg], 1);
    g_order[pos] = e;
}

__global__ void node_kernel(int m) {
    int gw = (blockIdx.x * blockDim.x + threadIdx.x) >> 5;
    int lane = threadIdx.x & 31;
    if (gw >= NN) return;
    int n = gw;
    int deg = g_counts[n];
    int start = g_offsets[n];
    float mx[4] = {-FLT_MAX, -FLT_MAX, -FLT_MAX, -FLT_MAX};
    for (int i = lane; i < deg; i += 32) {
        int e = g_order[start + i];
        float4 a = reinterpret_cast<const float4*>(g_a)[e];
        mx[0] = fmaxf(mx[0], a.x); mx[1] = fmaxf(mx[1], a.y);
        mx[2] = fmaxf(mx[2], a.z); mx[3] = fmaxf(mx[3], a.w);
    }
#pragma unroll
    for (int h = 0; h < 4; h++) mx[h] = wredmax(mx[h]);
    float sm4[4] = {0.f, 0.f, 0.f, 0.f};
    for (int i = lane; i < deg; i += 32) {
        int e = g_order[start + i];
        float4 a = reinterpret_cast<const float4*>(g_a)[e];
        sm4[0] += expf(a.x - mx[0]); sm4[1] += expf(a.y - mx[1]);
        sm4[2] += expf(a.z - mx[2]); sm4[3] += expf(a.w - mx[3]);
    }
    float inv[4];
#pragma unroll
    for (int h = 0; h < 4; h++) {
        sm4[h] = wredsum(sm4[h]);
        inv[h] = (deg > 0) ? (1.f / sm4[h]) : 0.f;
    }
    float acc[8];
#pragma unroll
    for (int t = 0; t < 8; t++) acc[t] = 0.f;
    for (int i = 0; i < deg; i++) {
        int e = g_order[start + i];
        float4 a = reinterpret_cast<const float4*>(g_a)[e];
        float wv[4];
        wv[0] = expf(a.x - mx[0]) * inv[0];
        wv[1] = expf(a.y - mx[1]) * inv[1];
        wv[2] = expf(a.z - mx[2]) * inv[2];
        wv[3] = expf(a.w - mx[3]) * inv[3];
        const float* er = g_eft + (size_t)e * 64;
#pragma unroll
        for (int t = 0; t < 8; t++) {
            int k = lane + 32 * (t & 1);
            acc[t] += wv[t >> 1] * er[k];
        }
    }
    float* zr = g_z + (size_t)n * 512 + m * 256;
    __nv_bfloat16* zb = g_zb + ((size_t)n * 2 + m) * 256;
#pragma unroll
    for (int t = 0; t < 8; t++) {
        float v = celu3f(acc[t]);
        zr[lane + 32 * t] = v;
        zb[lane + 32 * t] = __float2bfloat16(v);
    }
}

// ---------------- tensor-core MLP via mma.sync (plain sm_103 path) ----------------
// 512 threads = 16 warps as 4(m) x 4(n). Per CTA: 128 rows.
// SMEM: A [128][264] bf16 (67584 B), W [256][264] bf16 (135168 B), biases, red.
// Row stride 528 B = 33*16B -> ldmatrix conflict-free.
#define SSTRIDE 528
#define OFF_W   67584
#define OFF_FB1 202752
#define OFF_FB2 203776
#define OFF_FW3 204288
#define OFF_RED 204800
#define SMEM_MLP 204928

__global__ __launch_bounds__(512, 1) void mlp_mma_kernel(
    const float* __restrict__ fb1, const float* __restrict__ fb2,
    const float* __restrict__ fw3) {
    extern __shared__ char smem[];
    char* sa = smem;
    char* sw = smem + OFF_W;
    float* fb1s = reinterpret_cast<float*>(smem + OFF_FB1);
    float* fb2s = reinterpret_cast<float*>(smem + OFF_FB2);
    float* fw3s = reinterpret_cast<float*>(smem + OFF_FW3);
    float* red  = reinterpret_cast<float*>(smem + OFF_RED);

    uint32_t sa_u = smem_to_u32(sa);
    uint32_t sw_u = sa_u + OFF_W;

    int tid = threadIdx.x;
    int wid = tid >> 5;
    int lane = tid & 31;
    int wm = wid >> 2;      // 0..3  -> rows m_base = wm*32
    int wn = wid & 3;       // 0..3
    int m_base = wm * 32;
    int rowbase = blockIdx.x * 128;
    int g = lane >> 2;      // group id 0..7
    int tig = lane & 3;     // thread in group

    // ---- stage biases ----
    for (int i = tid; i < 256; i += 512) fb1s[i] = fb1[i];
    for (int i = tid; i < 128; i += 512) { fb2s[i] = fb2[i]; fw3s[i] = fw3[i]; }

    // ---- load A (z rows bf16, zero-pad) ----
    for (int idx = tid; idx < 4096; idx += 512) {
        int r = idx >> 5, c = idx & 31;
        int grow = rowbase + r;
        uint4 v = make_uint4(0, 0, 0, 0);
        if (grow < ROWS_TOT)
            v = *reinterpret_cast<const uint4*>(g_zb + (size_t)grow * 256 + c * 8);
        *reinterpret_cast<uint4*>(sa + r * SSTRIDE + c * 16) = v;
    }
    // ---- load W1 (256 rows) ----
    for (int idx = tid; idx < 8192; idx += 512) {
        int r = idx >> 5, c = idx & 31;
        uint4 v = *reinterpret_cast<const uint4*>(g_fw1b + r * 256 + c * 8);
        *reinterpret_cast<uint4*>(sw + r * SSTRIDE + c * 16) = v;
    }
    __syncthreads();

    // ---- layer 1: C[128x256] = A @ W1^T ; warp tile 32x64 ----
    float acc[2][8][4];
#pragma unroll
    for (int mt = 0; mt < 2; mt++)
#pragma unroll
        for (int nt = 0; nt < 8; nt++)
#pragma unroll
            for (int c = 0; c < 4; c++) acc[mt][nt][c] = 0.f;

    {
        int n_base = wn * 64;
        // ldmatrix lane address components (constant across k except k offset)
        int arow = m_base + (lane & 15);            // + mt*16
        int acol8 = ((lane >> 4) & 1) * 8;
        int brow = n_base + ((lane >> 4) & 1) * 8 + (lane & 7);  // + np*16
        int bcol8 = ((lane >> 3) & 1) * 8;
#pragma unroll
        for (int k = 0; k < 256; k += 16) {
            uint32_t afrag[2][4];
#pragma unroll
            for (int mt = 0; mt < 2; mt++)
                ldsm_x4(sa_u + (arow + mt * 16) * SSTRIDE + (k + acol8) * 2, afrag[mt]);
#pragma unroll
            for (int np = 0; np < 4; np++) {
                uint32_t bfrag[4];
                ldsm_x4(sw_u + (brow + np * 16) * SSTRIDE + (k + bcol8) * 2, bfrag);
#pragma unroll
                for (int mt = 0; mt < 2; mt++) {
                    mma_bf16(acc[mt][np * 2],     afrag[mt], bfrag);
                    mma_bf16(acc[mt][np * 2 + 1], afrag[mt], bfrag + 2);
                }
            }
        }
    }
    __syncthreads();   // everyone done reading A (z) and W1

    // ---- epilogue 1: t1 = celu3(C + fb1) -> bf16 back into A region ----
    {
        int n_base = wn * 64;
#pragma unroll
        for (int mt = 0; mt < 2; mt++) {
#pragma unroll
            for (int nt = 0; nt < 8; nt++) {
                int row = m_base + mt * 16 + g;
                int col = n_base + nt * 8 + tig * 2;
                float b0 = fb1s[col], b1 = fb1s[col + 1];
                float t0 = celu3f(acc[mt][nt][0] + b0);
                float t1 = celu3f(acc[mt][nt][1] + b1);
                float t2 = celu3f(acc[mt][nt][2] + b0);
                float t3 = celu3f(acc[mt][nt][3] + b1);
                __nv_bfloat162 p01 = __floats2bfloat162_rn(t0, t1);
                __nv_bfloat162 p23 = __floats2bfloat162_rn(t2, t3);
                *reinterpret_cast<uint32_t*>(sa + row * SSTRIDE + col * 2) =
                    *reinterpret_cast<uint32_t*>(&p01);
                *reinterpret_cast<uint32_t*>(sa + (row + 8) * SSTRIDE + col * 2) =
                    *reinterpret_cast<uint32_t*>(&p23);
            }
        }
    }
    // ---- load W2 (128 rows) over W1 ----
    for (int idx = tid; idx < 4096; idx += 512) {
        int r = idx >> 5, c = idx & 31;
        uint4 v = *reinterpret_cast<const uint4*>(g_fw2b + r * 256 + c * 8);
        *reinterpret_cast<uint4*>(sw + r * SSTRIDE + c * 16) = v;
    }
    __syncthreads();

    // ---- layer 2: C2[128x128] = t1 @ W2^T ; warp tile 32x32 ----
    float acc2[2][4][4];
#pragma unroll
    for (int mt = 0; mt < 2; mt++)
#pragma unroll
        for (int nt = 0; nt < 4; nt++)
#pragma unroll
            for (int c = 0; c < 4; c++) acc2[mt][nt][c] = 0.f;

    {
        int n_base = wn * 32;
        int arow = m_base + (lane & 15);
        int acol8 = ((lane >> 4) & 1) * 8;
        int brow = n_base + ((lane >> 4) & 1) * 8 + (lane & 7);
        int bcol8 = ((lane >> 3) & 1) * 8;
#pragma unroll
        for (int k = 0; k < 256; k += 16) {
            uint32_t afrag[2][4];
#pragma unroll
            for (int mt = 0; mt < 2; mt++)
                ldsm_x4(sa_u + (arow + mt * 16) * SSTRIDE + (k + acol8) * 2, afrag[mt]);
#pragma unroll
            for (int np = 0; np < 2; np++) {
                uint32_t bfrag[4];
                ldsm_x4(sw_u + (brow + np * 16) * SSTRIDE + (k + bcol8) * 2, bfrag);
#pragma unroll
                for (int mt = 0; mt < 2; mt++) {
                    mma_bf16(acc2[mt][np * 2],     afrag[mt], bfrag);
                    mma_bf16(acc2[mt][np * 2 + 1], afrag[mt], bfrag + 2);
                }
            }
        }
    }

    // ---- epilogue 2: per-row w = sum_c celu3(C2 + fb2)*fw3 ; reduce by path parity ----
    {
        int n_base = wn * 32;
        float ws0 = 0.f, ws1 = 0.f;
        int p = g & 1;   // path parity of this thread's rows
#pragma unroll
        for (int mt = 0; mt < 2; mt++) {
            int row0 = rowbase + m_base + mt * 16 + g;
            int row1 = row0 + 8;
            float s = 0.f;
#pragma unroll
            for (int nt = 0; nt < 4; nt++) {
                int col = n_base + nt * 8 + tig * 2;
                float b0 = fb2s[col], b1 = fb2s[col + 1];
                float w0 = fw3s[col], w1 = fw3s[col + 1];
                float sA = celu3f(acc2[mt][nt][0] + b0) * w0 + celu3f(acc2[mt][nt][1] + b1) * w1;
                float sB = celu3f(acc2[mt][nt][2] + b0) * w0 + celu3f(acc2[mt][nt][3] + b1) * w1;
                if (row0 < ROWS_TOT) s += sA;
                if (row1 < ROWS_TOT) s += sB;
            }
            if (p) ws1 += s; else ws0 += s;
        }
        ws0 = wredsum(ws0);
        ws1 = wredsum(ws1);
        if (lane == 0) { red[wid * 2] = ws0; red[wid * 2 + 1] = ws1; }
    }
    __syncthreads();
    if (tid == 0) {
        float s0 = 0.f, s1 = 0.f;
#pragma unroll
        for (int w = 0; w < 16; w++) { s0 += red[w * 2]; s1 += red[w * 2 + 1]; }
        atomicAdd(&g_w[0], s0);
        atomicAdd(&g_w[1], s1);
    }
}

__global__ void beta_kernel() {
    float w0 = g_w[0] * (1.f / (float)NN);
    float w1 = g_w[1] * (1.f / (float)NN);
    float mx = fmaxf(w0, w1);
    float e0 = expf(w0 - mx), e1 = expf(w1 - mx);
    float inv = 1.f / (e0 + e1);
    g_beta[0] = e0 * inv;
    g_beta[1] = e1 * inv;
}

__global__ void final_kernel(float* __restrict__ out) {
    int idx = blockIdx.x * blockDim.x + threadIdx.x;
    if (idx >= NN * 64) return;
    int n = idx >> 6;
    int q = idx & 63;
    float4 z0 = reinterpret_cast<const float4*>(g_z)[(size_t)n * 128 + q];
    float4 z1 = reinterpret_cast<const float4*>(g_z)[(size_t)n * 128 + 64 + q];
    float b0 = g_beta[0], b1 = g_beta[1];
    float4 o;
    o.x = b0 * z0.x + b1 * z1.x;
    o.y = b0 * z0.y + b1 * z1.y;
    o.z = b0 * z0.z + b1 * z1.z;
    o.w = b0 * z0.w + b1 * z1.w;
    reinterpret_cast<float4*>(out)[idx] = o;
}

// ---------------- launch ----------------
extern "C" void kernel_launch(void* const* d_in, const int* in_sizes, int n_in,
                              void* d_out, int out_size) {
    const float* feat    = (const float*)d_in[0];
    const float* r_vec   = (const float*)d_in[1];
    const float* attn1_w = (const float*)d_in[2];
    const float* attn2   = (const float*)d_in[3];
    const float* fw1     = (const float*)d_in[4];
    const float* fb1     = (const float*)d_in[5];
    const float* fw2     = (const float*)d_in[6];
    const float* fb2     = (const float*)d_in[7];
    const float* fw3     = (const float*)d_in[8];
    const int*   inst    = (const int*)d_in[9];
    float* out = (float*)d_out;

    void* cptr = nullptr;
    cudaGetSymbolAddress(&cptr, g_counts);

    const int SCAN_BLOCKS = (NN + 1023) / 1024;

    init_kernel<<<1, 64>>>(r_vec);
    wconv_kernel<<<(256 * 256 + 255) / 256, 256>>>(fw1, fw2);
    a1n_kernel<<<(NN * 32 + 255) / 256, 256>>>(feat, attn1_w);

    for (int m = 0; m < 2; m++) {
        cudaMemsetAsync(cptr, 0, NN * sizeof(int));
        edge_kernel<<<(EE * 32 + 255) / 256, 256>>>(feat, inst, attn2, m);
        scan1_kernel<<<SCAN_BLOCKS, 1024>>>();
        scan2_kernel<<<1, 1>>>(SCAN_BLOCKS);
        scan3_kernel<<<SCAN_BLOCKS, 1024>>>();
        scatter_kernel<<<(EE + 255) / 256, 256>>>(inst, m);
        node_kernel<<<(NN * 32 + 255) / 256, 256>>>(m);
    }

    cudaFuncSetAttribute(mlp_mma_kernel, cudaFuncAttributeMaxDynamicSharedMemorySize, SMEM_MLP);
    mlp_mma_kernel<<<MLP_CTAS, 512, SMEM_MLP>>>(fb1, fb2, fw3);
    beta_kernel<<<1, 1>>>();
    final_kernel<<<(NN * 64 + 255) / 256, 256>>>(out);
}

// round 7
// speedup vs baseline: 2.9921x; 1.2369x over previous
#include <cuda_runtime.h>
#include <cuda_bf16.h>
#include <math.h>
#include <float.h>
#include <stdint.h>

// Problem constants (fixed by dataset)
#define NN 50000
#define HH 64
#define EE 250000
#define HEADS 4
#define TOT_E (2 * EE)             // edges across both paths
#define TOT_N (2 * NN)             // segments across both paths
#define ROWS_TOT (NN * 2)          // 100000 MLP rows (N nodes x 2 paths)
#define MLP_CTAS ((ROWS_TOT + 127) / 128)

// ---------------- scratch (static device memory; no allocs) ----------------
__device__ float g_fr[2][3][32][2];
__device__ float g_a1n[NN * 4];
__device__ float g_eft[(size_t)TOT_E * 64];   // CSR-sorted edge features
__device__ float g_a[(size_t)TOT_E * 4];      // CSR-sorted edge logits
__device__ int   g_counts[TOT_N];
__device__ int   g_offsets[TOT_N];
__device__ int   g_cursor[TOT_N];
__device__ int   g_part[128];
__device__ float g_z[(size_t)NN * 512];                       // fp32 (N, 2, 256)
__device__ __align__(16) __nv_bfloat16 g_zb[(size_t)ROWS_TOT * 256]; // bf16 rows
__device__ __align__(16) __nv_bfloat16 g_fw1b[256 * 256];
__device__ __align__(16) __nv_bfloat16 g_fw2b[128 * 256];
__device__ float g_w[2];
__device__ float g_beta[2];

// ---------------- helpers ----------------
// Fast celu(alpha=3): ~2ulp exp is fine at 1e-3 tolerance.
__device__ __forceinline__ float celu3f(float x) {
    return x > 0.f ? x : 3.f * (__expf(x * (1.f / 3.f)) - 1.f);
}
__device__ __forceinline__ float sigmf(float x) {
    return __fdividef(1.f, 1.f + __expf(-x));
}
__device__ __forceinline__ float wredsum(float v) {
#pragma unroll
    for (int o = 16; o; o >>= 1) v += __shfl_xor_sync(0xffffffffu, v, o);
    return v;
}
__device__ __forceinline__ float wredmax(float v) {
#pragma unroll
    for (int o = 16; o; o >>= 1) v = fmaxf(v, __shfl_xor_sync(0xffffffffu, v, o));
    return v;
}
__device__ __forceinline__ uint32_t smem_to_u32(const void* p) {
    uint32_t a;
    asm("{ .reg .u64 t; cvta.to.shared.u64 t, %1; cvt.u32.u64 %0, t; }" : "=r"(a) : "l"(p));
    return a;
}

// ldmatrix x4 (four 8x8 b16 tiles)
__device__ __forceinline__ void ldsm_x4(uint32_t addr, uint32_t* r) {
    asm volatile("ldmatrix.sync.aligned.m8n8.x4.shared.b16 {%0,%1,%2,%3}, [%4];"
                 : "=r"(r[0]), "=r"(r[1]), "=r"(r[2]), "=r"(r[3]) : "r"(addr));
}
// mma m16n8k16 bf16 -> f32 accum (in place)
__device__ __forceinline__ void mma_bf16(float* d, const uint32_t* a, const uint32_t* b) {
    asm volatile(
        "mma.sync.aligned.m16n8k16.row.col.f32.bf16.bf16.f32 "
        "{%0,%1,%2,%3}, {%4,%5,%6,%7}, {%8,%9}, {%0,%1,%2,%3};"
        : "+f"(d[0]), "+f"(d[1]), "+f"(d[2]), "+f"(d[3])
        : "r"(a[0]), "r"(a[1]), "r"(a[2]), "r"(a[3]), "r"(b[0]), "r"(b[1]));
}

// ---------------- kernels ----------------

__global__ void init_kernel(const float* __restrict__ r_vec) {
    int t = threadIdx.x;
    if (t < 2) g_w[t] = 0.f;
    if (t < 32) {
        float nre[4], nim[4];
#pragma unroll
        for (int r = 0; r < 4; r++) {
            float re = r_vec[r * 64 + t * 2];
            float im = r_vec[r * 64 + t * 2 + 1];
            float inv = rsqrtf(re * re + im * im);
            nre[r] = re * inv;
            nim[r] = im * inv;
        }
#pragma unroll
        for (int m = 0; m < 2; m++) {
            int a = 2 * m + 1, b = 2 * m;
            g_fr[m][2][t][0] = 1.f; g_fr[m][2][t][1] = 0.f;
            g_fr[m][1][t][0] = nre[a]; g_fr[m][1][t][1] = nim[a];
            g_fr[m][0][t][0] = nre[a] * nre[b] - nim[a] * nim[b];
            g_fr[m][0][t][1] = nre[a] * nim[b] + nim[a] * nre[b];
        }
    }
}

__global__ void wconv_kernel(const float* __restrict__ fw1, const float* __restrict__ fw2) {
    int i = blockIdx.x * blockDim.x + threadIdx.x;
    if (i < 256 * 256) g_fw1b[i] = __float2bfloat16(fw1[i]);
    if (i < 128 * 256) g_fw2b[i] = __float2bfloat16(fw2[i]);
}

__global__ void a1n_kernel(const float* __restrict__ feat, const float* __restrict__ aw) {
    int gw = (blockIdx.x * blockDim.x + threadIdx.x) >> 5;
    int lane = threadIdx.x & 31;
    if (gw >= NN) return;
    float2 d = reinterpret_cast<const float2*>(feat)[gw * 32 + lane];
    float p[4];
#pragma unroll
    for (int h = 0; h < 4; h++) {
        float v = aw[h * 64 + 2 * lane] * d.x + aw[h * 64 + 2 * lane + 1] * d.y;
        p[h] = wredsum(v);
    }
    if (lane == 0) {
        float4 r;
        r.x = celu3f(p[0]); r.y = celu3f(p[1]); r.z = celu3f(p[2]); r.w = celu3f(p[3]);
        reinterpret_cast<float4*>(g_a1n)[gw] = r;
    }
}

// Histogram segment counts for both paths in one pass.
__global__ void count_kernel(const int* __restrict__ inst) {
    int idx = blockIdx.x * blockDim.x + threadIdx.x;
    if (idx >= TOT_E) return;
    int m = idx >= EE;
    int e = idx - m * EE;
    int seg = inst[(size_t)m * EE * 3 + (size_t)e * 3];
    atomicAdd(&g_counts[m * NN + seg], 1);
}

__global__ void scan1_kernel() {
    __shared__ int s[1024];
    int t = threadIdx.x;
    int i = blockIdx.x * 1024 + t;
    int v = (i < TOT_N) ? g_counts[i] : 0;
    s[t] = v;
    __syncthreads();
    for (int off = 1; off < 1024; off <<= 1) {
        int x = (t >= off) ? s[t - off] : 0;
        __syncthreads();
        s[t] += x;
        __syncthreads();
    }
    if (i < TOT_N) g_offsets[i] = s[t] - v;
    if (t == 1023) g_part[blockIdx.x] = s[1023];
}
__global__ void scan2_kernel(int nblk) {
    int run = 0;
    for (int b = 0; b < nblk; b++) { int x = g_part[b]; g_part[b] = run; run += x; }
}
__global__ void scan3_kernel() {
    int i = blockIdx.x * 1024 + threadIdx.x;
    if (i < TOT_N) {
        int o = g_offsets[i] + g_part[blockIdx.x];
        g_offsets[i] = o;
        g_cursor[i] = o;
    }
}

// Per-edge (both paths): gather, rotate, gate -> eft; logits -> a.
// Writes directly to CSR-sorted position (no separate scatter pass).
__global__ void edge_kernel(const float* __restrict__ feat, const int* __restrict__ inst,
                            const float* __restrict__ attn2) {
    int gw = (blockIdx.x * blockDim.x + threadIdx.x) >> 5;
    int lane = threadIdx.x & 31;
    if (gw >= TOT_E) return;
    int m = gw >= EE;
    int e = gw - m * EE;
    const int* ip = inst + (size_t)m * EE * 3 + (size_t)e * 3;
    int n0 = ip[0];
    float mre = 0.f, mim = 0.f;
#pragma unroll
    for (int p = 0; p < 3; p++) {
        int np = ip[p];
        float2 d = reinterpret_cast<const float2*>(feat)[np * 32 + lane];
        float fre = g_fr[m][p][lane][0];
        float fim = g_fr[m][p][lane][1];
        mre += d.x * fre - d.y * fim;
        mim += d.x * fim + d.y * fre;
    }
    mre *= (1.f / 3.f); mim *= (1.f / 3.f);
    float sx = celu3f(mre) * sigmf(mre);
    float sy = celu3f(mim) * sigmf(mim);
    float ex_ = celu3f(sx);
    float ey_ = celu3f(sy);
    float a2[4];
#pragma unroll
    for (int h = 0; h < 4; h++) {
        float v = attn2[h * 64 + 2 * lane] * ex_ + attn2[h * 64 + 2 * lane + 1] * ey_;
        a2[h] = wredsum(v);
    }
    int pos = 0;
    if (lane == 0) pos = atomicAdd(&g_cursor[m * NN + n0], 1);
    pos = __shfl_sync(0xffffffffu, pos, 0);
    reinterpret_cast<float2*>(g_eft)[(size_t)pos * 32 + lane] = make_float2(ex_, ey_);
    if (lane == 0) {
        float4 a1 = reinterpret_cast<const float4*>(g_a1n)[n0];
        float4 av;
        av.x = celu3f(a1.x + a2[0]);
        av.y = celu3f(a1.y + a2[1]);
        av.z = celu3f(a1.z + a2[2]);
        av.w = celu3f(a1.w + a2[3]);
        reinterpret_cast<float4*>(g_a)[pos] = av;
    }
}

// One warp per (path, node): segment softmax + weighted sum over CONTIGUOUS rows.
__global__ void node_kernel() {
    int gw = (blockIdx.x * blockDim.x + threadIdx.x) >> 5;
    int lane = threadIdx.x & 31;
    if (gw >= TOT_N) return;
    int m = gw >= NN;
    int n = gw - m * NN;
    int deg = g_counts[gw];
    int start = g_offsets[gw];
    float mx[4] = {-FLT_MAX, -FLT_MAX, -FLT_MAX, -FLT_MAX};
    for (int i = lane; i < deg; i += 32) {
        float4 a = reinterpret_cast<const float4*>(g_a)[start + i];
        mx[0] = fmaxf(mx[0], a.x); mx[1] = fmaxf(mx[1], a.y);
        mx[2] = fmaxf(mx[2], a.z); mx[3] = fmaxf(mx[3], a.w);
    }
#pragma unroll
    for (int h = 0; h < 4; h++) mx[h] = wredmax(mx[h]);
    float sm4[4] = {0.f, 0.f, 0.f, 0.f};
    for (int i = lane; i < deg; i += 32) {
        float4 a = reinterpret_cast<const float4*>(g_a)[start + i];
        sm4[0] += __expf(a.x - mx[0]); sm4[1] += __expf(a.y - mx[1]);
        sm4[2] += __expf(a.z - mx[2]); sm4[3] += __expf(a.w - mx[3]);
    }
    float inv[4];
#pragma unroll
    for (int h = 0; h < 4; h++) {
        sm4[h] = wredsum(sm4[h]);
        inv[h] = (deg > 0) ? __fdividef(1.f, sm4[h]) : 0.f;
    }
    float acc[8];
#pragma unroll
    for (int t = 0; t < 8; t++) acc[t] = 0.f;
    const float* ebase = g_eft + (size_t)start * 64;
    for (int i = 0; i < deg; i++) {
        float4 a = reinterpret_cast<const float4*>(g_a)[start + i];
        float w0 = __expf(a.x - mx[0]) * inv[0];
        float w1 = __expf(a.y - mx[1]) * inv[1];
        float w2 = __expf(a.z - mx[2]) * inv[2];
        float w3 = __expf(a.w - mx[3]) * inv[3];
        float e0 = ebase[(size_t)i * 64 + lane];
        float e1 = ebase[(size_t)i * 64 + lane + 32];
        acc[0] += w0 * e0; acc[1] += w0 * e1;
        acc[2] += w1 * e0; acc[3] += w1 * e1;
        acc[4] += w2 * e0; acc[5] += w2 * e1;
        acc[6] += w3 * e0; acc[7] += w3 * e1;
    }
    float* zr = g_z + (size_t)n * 512 + m * 256;
    __nv_bfloat16* zb = g_zb + ((size_t)n * 2 + m) * 256;
#pragma unroll
    for (int t = 0; t < 8; t++) {
        float v = celu3f(acc[t]);
        int k = (t >> 1) * 64 + (t & 1) * 32 + lane;
        zr[k] = v;
        zb[k] = __float2bfloat16(v);
    }
}

// ---------------- tensor-core MLP via mma.sync ----------------
#define SSTRIDE 528
#define OFF_W   67584
#define OFF_FB1 202752
#define OFF_FB2 203776
#define OFF_FW3 204288
#define OFF_RED 204800
#define SMEM_MLP 204928

__global__ __launch_bounds__(512, 1) void mlp_mma_kernel(
    const float* __restrict__ fb1, const float* __restrict__ fb2,
    const float* __restrict__ fw3) {
    extern __shared__ char smem[];
    char* sa = smem;
    char* sw = smem + OFF_W;
    float* fb1s = reinterpret_cast<float*>(smem + OFF_FB1);
    float* fb2s = reinterpret_cast<float*>(smem + OFF_FB2);
    float* fw3s = reinterpret_cast<float*>(smem + OFF_FW3);
    float* red  = reinterpret_cast<float*>(smem + OFF_RED);

    uint32_t sa_u = smem_to_u32(sa);
    uint32_t sw_u = sa_u + OFF_W;

    int tid = threadIdx.x;
    int wid = tid >> 5;
    int lane = tid & 31;
    int wm = wid >> 2;
    int wn = wid & 3;
    int m_base = wm * 32;
    int rowbase = blockIdx.x * 128;
    int g = lane >> 2;
    int tig = lane & 3;

    for (int i = tid; i < 256; i += 512) fb1s[i] = fb1[i];
    for (int i = tid; i < 128; i += 512) { fb2s[i] = fb2[i]; fw3s[i] = fw3[i]; }

    for (int idx = tid; idx < 4096; idx += 512) {
        int r = idx >> 5, c = idx & 31;
        int grow = rowbase + r;
        uint4 v = make_uint4(0, 0, 0, 0);
        if (grow < ROWS_TOT)
            v = *reinterpret_cast<const uint4*>(g_zb + (size_t)grow * 256 + c * 8);
        *reinterpret_cast<uint4*>(sa + r * SSTRIDE + c * 16) = v;
    }
    for (int idx = tid; idx < 8192; idx += 512) {
        int r = idx >> 5, c = idx & 31;
        uint4 v = *reinterpret_cast<const uint4*>(g_fw1b + r * 256 + c * 8);
        *reinterpret_cast<uint4*>(sw + r * SSTRIDE + c * 16) = v;
    }
    __syncthreads();

    float acc[2][8][4];
#pragma unroll
    for (int mt = 0; mt < 2; mt++)
#pragma unroll
        for (int nt = 0; nt < 8; nt++)
#pragma unroll
            for (int c = 0; c < 4; c++) acc[mt][nt][c] = 0.f;

    {
        int n_base = wn * 64;
        int arow = m_base + (lane & 15);
        int acol8 = ((lane >> 4) & 1) * 8;
        int brow = n_base + ((lane >> 4) & 1) * 8 + (lane & 7);
        int bcol8 = ((lane >> 3) & 1) * 8;
#pragma unroll
        for (int k = 0; k < 256; k += 16) {
            uint32_t afrag[2][4];
#pragma unroll
            for (int mt = 0; mt < 2; mt++)
                ldsm_x4(sa_u + (arow + mt * 16) * SSTRIDE + (k + acol8) * 2, afrag[mt]);
#pragma unroll
            for (int np = 0; np < 4; np++) {
                uint32_t bfrag[4];
                ldsm_x4(sw_u + (brow + np * 16) * SSTRIDE + (k + bcol8) * 2, bfrag);
#pragma unroll
                for (int mt = 0; mt < 2; mt++) {
                    mma_bf16(acc[mt][np * 2],     afrag[mt], bfrag);
                    mma_bf16(acc[mt][np * 2 + 1], afrag[mt], bfrag + 2);
                }
            }
        }
    }
    __syncthreads();

    {
        int n_base = wn * 64;
#pragma unroll
        for (int mt = 0; mt < 2; mt++) {
#pragma unroll
            for (int nt = 0; nt < 8; nt++) {
                int row = m_base + mt * 16 + g;
                int col = n_base + nt * 8 + tig * 2;
                float b0 = fb1s[col], b1 = fb1s[col + 1];
                float t0 = celu3f(acc[mt][nt][0] + b0);
                float t1 = celu3f(acc[mt][nt][1] + b1);
                float t2 = celu3f(acc[mt][nt][2] + b0);
                float t3 = celu3f(acc[mt][nt][3] + b1);
                __nv_bfloat162 p01 = __floats2bfloat162_rn(t0, t1);
                __nv_bfloat162 p23 = __floats2bfloat162_rn(t2, t3);
                *reinterpret_cast<uint32_t*>(sa + row * SSTRIDE + col * 2) =
                    *reinterpret_cast<uint32_t*>(&p01);
                *reinterpret_cast<uint32_t*>(sa + (row + 8) * SSTRIDE + col * 2) =
                    *reinterpret_cast<uint32_t*>(&p23);
            }
        }
    }
    for (int idx = tid; idx < 4096; idx += 512) {
        int r = idx >> 5, c = idx & 31;
        uint4 v = *reinterpret_cast<const uint4*>(g_fw2b + r * 256 + c * 8);
        *reinterpret_cast<uint4*>(sw + r * SSTRIDE + c * 16) = v;
    }
    __syncthreads();

    float acc2[2][4][4];
#pragma unroll
    for (int mt = 0; mt < 2; mt++)
#pragma unroll
        for (int nt = 0; nt < 4; nt++)
#pragma unroll
            for (int c = 0; c < 4; c++) acc2[mt][nt][c] = 0.f;

    {
        int n_base = wn * 32;
        int arow = m_base + (lane & 15);
        int acol8 = ((lane >> 4) & 1) * 8;
        int brow = n_base + ((lane >> 4) & 1) * 8 + (lane & 7);
        int bcol8 = ((lane >> 3) & 1) * 8;
#pragma unroll
        for (int k = 0; k < 256; k += 16) {
            uint32_t afrag[2][4];
#pragma unroll
            for (int mt = 0; mt < 2; mt++)
                ldsm_x4(sa_u + (arow + mt * 16) * SSTRIDE + (k + acol8) * 2, afrag[mt]);
#pragma unroll
            for (int np = 0; np < 2; np++) {
                uint32_t bfrag[4];
                ldsm_x4(sw_u + (brow + np * 16) * SSTRIDE + (k + bcol8) * 2, bfrag);
#pragma unroll
                for (int mt = 0; mt < 2; mt++) {
                    mma_bf16(acc2[mt][np * 2],     afrag[mt], bfrag);
                    mma_bf16(acc2[mt][np * 2 + 1], afrag[mt], bfrag + 2);
                }
            }
        }
    }

    {
        int n_base = wn * 32;
        float ws0 = 0.f, ws1 = 0.f;
        int p = g & 1;
#pragma unroll
        for (int mt = 0; mt < 2; mt++) {
            int row0 = rowbase + m_base + mt * 16 + g;
            int row1 = row0 + 8;
            float s = 0.f;
#pragma unroll
            for (int nt = 0; nt < 4; nt++) {
                int col = n_base + nt * 8 + tig * 2;
                float b0 = fb2s[col], b1 = fb2s[col + 1];
                float w0 = fw3s[col], w1 = fw3s[col + 1];
                float sA = celu3f(acc2[mt][nt][0] + b0) * w0 + celu3f(acc2[mt][nt][1] + b1) * w1;
                float sB = celu3f(acc2[mt][nt][2] + b0) * w0 + celu3f(acc2[mt][nt][3] + b1) * w1;
                if (row0 < ROWS_TOT) s += sA;
                if (row1 < ROWS_TOT) s += sB;
            }
            if (p) ws1 += s; else ws0 += s;
        }
        ws0 = wredsum(ws0);
        ws1 = wredsum(ws1);
        if (lane == 0) { red[wid * 2] = ws0; red[wid * 2 + 1] = ws1; }
    }
    __syncthreads();
    if (tid == 0) {
        float s0 = 0.f, s1 = 0.f;
#pragma unroll
        for (int w = 0; w < 16; w++) { s0 += red[w * 2]; s1 += red[w * 2 + 1]; }
        atomicAdd(&g_w[0], s0);
        atomicAdd(&g_w[1], s1);
    }
}

__global__ void beta_kernel() {
    float w0 = g_w[0] * (1.f / (float)NN);
    float w1 = g_w[1] * (1.f / (float)NN);
    float mx = fmaxf(w0, w1);
    float e0 = expf(w0 - mx), e1 = expf(w1 - mx);
    float inv = 1.f / (e0 + e1);
    g_beta[0] = e0 * inv;
    g_beta[1] = e1 * inv;
}

__global__ void final_kernel(float* __restrict__ out) {
    int idx = blockIdx.x * blockDim.x + threadIdx.x;
    if (idx >= NN * 64) return;
    int n = idx >> 6;
    int q = idx & 63;
    float4 z0 = reinterpret_cast<const float4*>(g_z)[(size_t)n * 128 + q];
    float4 z1 = reinterpret_cast<const float4*>(g_z)[(size_t)n * 128 + 64 + q];
    float b0 = g_beta[0], b1 = g_beta[1];
    float4 o;
    o.x = b0 * z0.x + b1 * z1.x;
    o.y = b0 * z0.y + b1 * z1.y;
    o.z = b0 * z0.z + b1 * z1.z;
    o.w = b0 * z0.w + b1 * z1.w;
    reinterpret_cast<float4*>(out)[idx] = o;
}

// ---------------- launch ----------------
extern "C" void kernel_launch(void* const* d_in, const int* in_sizes, int n_in,
                              void* d_out, int out_size) {
    const float* feat    = (const float*)d_in[0];
    const float* r_vec   = (const float*)d_in[1];
    const float* attn1_w = (const float*)d_in[2];
    const float* attn2   = (const float*)d_in[3];
    const float* fw1     = (const float*)d_in[4];
    const float* fb1     = (const float*)d_in[5];
    const float* fw2     = (const float*)d_in[6];
    const float* fb2     = (const float*)d_in[7];
    const float* fw3     = (const float*)d_in[8];
    const int*   inst    = (const int*)d_in[9];
    float* out = (float*)d_out;

    void* cptr = nullptr;
    cudaGetSymbolAddress(&cptr, g_counts);

    const int SCAN_BLOCKS = (TOT_N + 1023) / 1024; // 98

    init_kernel<<<1, 64>>>(r_vec);
    wconv_kernel<<<(256 * 256 + 255) / 256, 256>>>(fw1, fw2);
    a1n_kernel<<<(NN * 32 + 255) / 256, 256>>>(feat, attn1_w);

    cudaMemsetAsync(cptr, 0, TOT_N * sizeof(int));
    count_kernel<<<(TOT_E + 255) / 256, 256>>>(inst);
    scan1_kernel<<<SCAN_BLOCKS, 1024>>>();
    scan2_kernel<<<1, 1>>>(SCAN_BLOCKS);
    scan3_kernel<<<SCAN_BLOCKS, 1024>>>();
    edge_kernel<<<(TOT_E * 32 + 255) / 256, 256>>>(feat, inst, attn2);
    node_kernel<<<(TOT_N * 32 + 255) / 256, 256>>>();

    cudaFuncSetAttribute(mlp_mma_kernel, cudaFuncAttributeMaxDynamicSharedMemorySize, SMEM_MLP);
    mlp_mma_kernel<<<MLP_CTAS, 512, SMEM_MLP>>>(fb1, fb2, fw3);
    beta_kernel<<<1, 1>>>();
    final_kernel<<<(NN * 64 + 255) / 256, 256>>>(out);
}

// round 8
// speedup vs baseline: 3.0529x; 1.0203x over previous
#include <cuda_runtime.h>
#include <cuda_bf16.h>
#include <math.h>
#include <float.h>
#include <stdint.h>

// Problem constants (fixed by dataset)
#define NN 50000
#define HH 64
#define EE 250000
#define HEADS 4
#define TOT_E (2 * EE)             // edges across both paths
#define TOT_N (2 * NN)             // segments across both paths
#define ROWS_TOT (NN * 2)          // 100000 MLP rows (N nodes x 2 paths)
#define MLP_CTAS ((ROWS_TOT + 127) / 128)

// ---------------- scratch (static device memory; no allocs) ----------------
__device__ float g_fr[2][3][32][2];
__device__ float g_a1n[NN * 4];
__device__ int   g_counts[TOT_N];
__device__ int   g_offsets[TOT_N];
__device__ int   g_cursor[TOT_N];
__device__ int   g_part[128];
__device__ __align__(16) int4 g_einst[TOT_E];  // CSR-sorted (n0,n1,n2,_) per edge
__device__ float g_z[(size_t)NN * 512];                       // fp32 (N, 2, 256)
__device__ __align__(16) __nv_bfloat16 g_zb[(size_t)ROWS_TOT * 256]; // bf16 rows
__device__ __align__(16) __nv_bfloat16 g_fw1b[256 * 256];
__device__ __align__(16) __nv_bfloat16 g_fw2b[128 * 256];
__device__ float g_w[2];
__device__ float g_beta[2];

// ---------------- helpers ----------------
__device__ __forceinline__ float celu3f(float x) {
    return x > 0.f ? x : 3.f * (__expf(x * (1.f / 3.f)) - 1.f);
}
__device__ __forceinline__ float sigmf(float x) {
    return __fdividef(1.f, 1.f + __expf(-x));
}
// gate(x) = celu3( celu3(x) * sigmoid(x) )
__device__ __forceinline__ float gatef(float x) {
    float se = celu3f(x) * sigmf(x);
    return celu3f(se);
}
__device__ __forceinline__ float wredsum(float v) {
#pragma unroll
    for (int o = 16; o; o >>= 1) v += __shfl_xor_sync(0xffffffffu, v, o);
    return v;
}
__device__ __forceinline__ uint32_t smem_to_u32(const void* p) {
    uint32_t a;
    asm("{ .reg .u64 t; cvta.to.shared.u64 t, %1; cvt.u32.u64 %0, t; }" : "=r"(a) : "l"(p));
    return a;
}

// ldmatrix x4 (four 8x8 b16 tiles)
__device__ __forceinline__ void ldsm_x4(uint32_t addr, uint32_t* r) {
    asm volatile("ldmatrix.sync.aligned.m8n8.x4.shared.b16 {%0,%1,%2,%3}, [%4];"
                 : "=r"(r[0]), "=r"(r[1]), "=r"(r[2]), "=r"(r[3]) : "r"(addr));
}
// mma m16n8k16 bf16 -> f32 accum (in place)
__device__ __forceinline__ void mma_bf16(float* d, const uint32_t* a, const uint32_t* b) {
    asm volatile(
        "mma.sync.aligned.m16n8k16.row.col.f32.bf16.bf16.f32 "
        "{%0,%1,%2,%3}, {%4,%5,%6,%7}, {%8,%9}, {%0,%1,%2,%3};"
        : "+f"(d[0]), "+f"(d[1]), "+f"(d[2]), "+f"(d[3])
        : "r"(a[0]), "r"(a[1]), "r"(a[2]), "r"(a[3]), "r"(b[0]), "r"(b[1]));
}

// ---------------- kernels ----------------

__global__ void init_kernel(const float* __restrict__ r_vec) {
    int t = threadIdx.x;
    if (t < 2) g_w[t] = 0.f;
    if (t < 32) {
        float nre[4], nim[4];
#pragma unroll
        for (int r = 0; r < 4; r++) {
            float re = r_vec[r * 64 + t * 2];
            float im = r_vec[r * 64 + t * 2 + 1];
            float inv = rsqrtf(re * re + im * im);
            nre[r] = re * inv;
            nim[r] = im * inv;
        }
#pragma unroll
        for (int m = 0; m < 2; m++) {
            int a = 2 * m + 1, b = 2 * m;
            g_fr[m][2][t][0] = 1.f; g_fr[m][2][t][1] = 0.f;
            g_fr[m][1][t][0] = nre[a]; g_fr[m][1][t][1] = nim[a];
            g_fr[m][0][t][0] = nre[a] * nre[b] - nim[a] * nim[b];
            g_fr[m][0][t][1] = nre[a] * nim[b] + nim[a] * nre[b];
        }
    }
}

__global__ void wconv_kernel(const float* __restrict__ fw1, const float* __restrict__ fw2) {
    int i = blockIdx.x * blockDim.x + threadIdx.x;
    if (i < 256 * 256) g_fw1b[i] = __float2bfloat16(fw1[i]);
    if (i < 128 * 256) g_fw2b[i] = __float2bfloat16(fw2[i]);
}

__global__ void a1n_kernel(const float* __restrict__ feat, const float* __restrict__ aw) {
    int gw = (blockIdx.x * blockDim.x + threadIdx.x) >> 5;
    int lane = threadIdx.x & 31;
    if (gw >= NN) return;
    float2 d = reinterpret_cast<const float2*>(feat)[gw * 32 + lane];
    float p[4];
#pragma unroll
    for (int h = 0; h < 4; h++) {
        float v = aw[h * 64 + 2 * lane] * d.x + aw[h * 64 + 2 * lane + 1] * d.y;
        p[h] = wredsum(v);
    }
    if (lane == 0) {
        float4 r;
        r.x = celu3f(p[0]); r.y = celu3f(p[1]); r.z = celu3f(p[2]); r.w = celu3f(p[3]);
        reinterpret_cast<float4*>(g_a1n)[gw] = r;
    }
}

// Histogram segment counts for both paths in one pass.
__global__ void count_kernel(const int* __restrict__ inst) {
    int idx = blockIdx.x * blockDim.x + threadIdx.x;
    if (idx >= TOT_E) return;
    int m = idx >= EE;
    int e = idx - m * EE;
    int seg = inst[(size_t)m * EE * 3 + (size_t)e * 3];
    atomicAdd(&g_counts[m * NN + seg], 1);
}

__global__ void scan1_kernel() {
    __shared__ int s[1024];
    int t = threadIdx.x;
    int i = blockIdx.x * 1024 + t;
    int v = (i < TOT_N) ? g_counts[i] : 0;
    s[t] = v;
    __syncthreads();
    for (int off = 1; off < 1024; off <<= 1) {
        int x = (t >= off) ? s[t - off] : 0;
        __syncthreads();
        s[t] += x;
        __syncthreads();
    }
    if (i < TOT_N) g_offsets[i] = s[t] - v;
    if (t == 1023) g_part[blockIdx.x] = s[1023];
}
__global__ void scan2_kernel(int nblk) {
    int run = 0;
    for (int b = 0; b < nblk; b++) { int x = g_part[b]; g_part[b] = run; run += x; }
}
__global__ void scan3_kernel() {
    int i = blockIdx.x * 1024 + threadIdx.x;
    if (i < TOT_N) {
        int o = g_offsets[i] + g_part[blockIdx.x];
        g_offsets[i] = o;
        g_cursor[i] = o;
    }
}

// Scatter node-id triplets into CSR order (one int4 per edge).
__global__ void scatter_kernel(const int* __restrict__ inst) {
    int idx = blockIdx.x * blockDim.x + threadIdx.x;
    if (idx >= TOT_E) return;
    int m = idx >= EE;
    int e = idx - m * EE;
    const int* ip = inst + (size_t)m * EE * 3 + (size_t)e * 3;
    int i0 = ip[0], i1 = ip[1], i2 = ip[2];
    int pos = atomicAdd(&g_cursor[m * NN + i0], 1);
    g_einst[pos] = make_int4(i0, i1, i2, 0);
}

// FUSED kernel: one warp per (path, node); 2x 16-lane subgroups, each processes
// one edge per iteration. Computes edge features on the fly (no g_eft round
// trip), accumulates un-shifted softmax (logits bounded: celu3 >= -3, Gaussian
// tails above), merges subgroups, writes z (fp32 + bf16).
__global__ __launch_bounds__(256) void node_fused_kernel(
    const float* __restrict__ feat, const float* __restrict__ attn2) {
    int gw = (blockIdx.x * blockDim.x + threadIdx.x) >> 5;
    int lane = threadIdx.x & 31;
    if (gw >= TOT_N) return;
    int m = gw >= NN;
    int n = gw - m * NN;
    int deg = g_counts[gw];
    int start = g_offsets[gw];
    int sub = lane >> 4;       // subgroup 0/1
    int li = lane & 15;        // lane within subgroup; owns feats 4li..4li+3

    // rotation factors for complex pairs 2li, 2li+1 (per path position)
    float2 fr0[3], fr1[3];
#pragma unroll
    for (int p = 0; p < 3; p++) {
        fr0[p] = *reinterpret_cast<const float2*>(&g_fr[m][p][2 * li][0]);
        fr1[p] = *reinterpret_cast<const float2*>(&g_fr[m][p][2 * li + 1][0]);
    }
    // attn2 slice for this lane's 4 feats, all 4 heads
    float4 at2[4];
#pragma unroll
    for (int h = 0; h < 4; h++)
        at2[h] = *reinterpret_cast<const float4*>(attn2 + h * 64 + 4 * li);
    float4 a1q = *reinterpret_cast<const float4*>(g_a1n + n * 4);
    float a1a[4] = {a1q.x, a1q.y, a1q.z, a1q.w};

    float acc[4][4];
    float den[4] = {0.f, 0.f, 0.f, 0.f};
#pragma unroll
    for (int h = 0; h < 4; h++)
#pragma unroll
        for (int j = 0; j < 4; j++) acc[h][j] = 0.f;

    int padded = (deg + 1) & ~1;   // equal trip counts for both subgroups
    for (int i = sub; i < padded; i += 2) {
        bool act = i < deg;
        int4 nd = g_einst[start + (act ? i : 0)];
        float mre0 = 0.f, mim0 = 0.f, mre1 = 0.f, mim1 = 0.f;
#pragma unroll
        for (int p = 0; p < 3; p++) {
            int np = (p == 0) ? nd.x : (p == 1) ? nd.y : nd.z;
            float4 d = *reinterpret_cast<const float4*>(feat + (size_t)np * 64 + 4 * li);
            mre0 += d.x * fr0[p].x - d.y * fr0[p].y;
            mim0 += d.x * fr0[p].y + d.y * fr0[p].x;
            mre1 += d.z * fr1[p].x - d.w * fr1[p].y;
            mim1 += d.z * fr1[p].y + d.w * fr1[p].x;
        }
        float ef[4];
        ef[0] = gatef(mre0 * (1.f / 3.f));
        ef[1] = gatef(mim0 * (1.f / 3.f));
        ef[2] = gatef(mre1 * (1.f / 3.f));
        ef[3] = gatef(mim1 * (1.f / 3.f));
        // per-head logit partials, butterfly within 16-lane subgroup
        float ph[4];
#pragma unroll
        for (int h = 0; h < 4; h++) {
            ph[h] = at2[h].x * ef[0] + at2[h].y * ef[1]
                  + at2[h].z * ef[2] + at2[h].w * ef[3];
#pragma unroll
            for (int o = 8; o; o >>= 1) ph[h] += __shfl_xor_sync(0xffffffffu, ph[h], o);
        }
#pragma unroll
        for (int h = 0; h < 4; h++) {
            float a = celu3f(a1a[h] + ph[h]);
            float wv = act ? __expf(a) : 0.f;
            den[h] += wv;
            acc[h][0] += wv * ef[0];
            acc[h][1] += wv * ef[1];
            acc[h][2] += wv * ef[2];
            acc[h][3] += wv * ef[3];
        }
    }
    // merge the two subgroups
#pragma unroll
    for (int h = 0; h < 4; h++) {
        den[h] += __shfl_xor_sync(0xffffffffu, den[h], 16);
#pragma unroll
        for (int j = 0; j < 4; j++)
            acc[h][j] += __shfl_xor_sync(0xffffffffu, acc[h][j], 16);
    }
    if (sub == 0) {
        float* zr = g_z + (size_t)n * 512 + m * 256;
        __nv_bfloat16* zb = g_zb + ((size_t)n * 2 + m) * 256;
#pragma unroll
        for (int h = 0; h < 4; h++) {
            float inv = (deg > 0) ? __fdividef(1.f, den[h]) : 0.f;
            float z0 = celu3f(acc[h][0] * inv);
            float z1 = celu3f(acc[h][1] * inv);
            float z2 = celu3f(acc[h][2] * inv);
            float z3 = celu3f(acc[h][3] * inv);
            *reinterpret_cast<float4*>(zr + h * 64 + 4 * li) = make_float4(z0, z1, z2, z3);
            __nv_bfloat162 b01 = __floats2bfloat162_rn(z0, z1);
            __nv_bfloat162 b23 = __floats2bfloat162_rn(z2, z3);
            *reinterpret_cast<uint32_t*>(zb + h * 64 + 4 * li) =
                *reinterpret_cast<uint32_t*>(&b01);
            *reinterpret_cast<uint32_t*>(zb + h * 64 + 4 * li + 2) =
                *reinterpret_cast<uint32_t*>(&b23);
        }
    }
}

// ---------------- tensor-core MLP via mma.sync ----------------
#define SSTRIDE 528
#define OFF_W   67584
#define OFF_FB1 202752
#define OFF_FB2 203776
#define OFF_FW3 204288
#define OFF_RED 204800
#define SMEM_MLP 204928

__global__ __launch_bounds__(512, 1) void mlp_mma_kernel(
    const float* __restrict__ fb1, const float* __restrict__ fb2,
    const float* __restrict__ fw3) {
    extern __shared__ char smem[];
    char* sa = smem;
    char* sw = smem + OFF_W;
    float* fb1s = reinterpret_cast<float*>(smem + OFF_FB1);
    float* fb2s = reinterpret_cast<float*>(smem + OFF_FB2);
    float* fw3s = reinterpret_cast<float*>(smem + OFF_FW3);
    float* red  = reinterpret_cast<float*>(smem + OFF_RED);

    uint32_t sa_u = smem_to_u32(sa);
    uint32_t sw_u = sa_u + OFF_W;

    int tid = threadIdx.x;
    int wid = tid >> 5;
    int lane = tid & 31;
    int wm = wid >> 2;
    int wn = wid & 3;
    int m_base = wm * 32;
    int rowbase = blockIdx.x * 128;
    int g = lane >> 2;
    int tig = lane & 3;

    for (int i = tid; i < 256; i += 512) fb1s[i] = fb1[i];
    for (int i = tid; i < 128; i += 512) { fb2s[i] = fb2[i]; fw3s[i] = fw3[i]; }

    for (int idx = tid; idx < 4096; idx += 512) {
        int r = idx >> 5, c = idx & 31;
        int grow = rowbase + r;
        uint4 v = make_uint4(0, 0, 0, 0);
        if (grow < ROWS_TOT)
            v = *reinterpret_cast<const uint4*>(g_zb + (size_t)grow * 256 + c * 8);
        *reinterpret_cast<uint4*>(sa + r * SSTRIDE + c * 16) = v;
    }
    for (int idx = tid; idx < 8192; idx += 512) {
        int r = idx >> 5, c = idx & 31;
        uint4 v = *reinterpret_cast<const uint4*>(g_fw1b + r * 256 + c * 8);
        *reinterpret_cast<uint4*>(sw + r * SSTRIDE + c * 16) = v;
    }
    __syncthreads();

    float acc[2][8][4];
#pragma unroll
    for (int mt = 0; mt < 2; mt++)
#pragma unroll
        for (int nt = 0; nt < 8; nt++)
#pragma unroll
            for (int c = 0; c < 4; c++) acc[mt][nt][c] = 0.f;

    {
        int n_base = wn * 64;
        int arow = m_base + (lane & 15);
        int acol8 = ((lane >> 4) & 1) * 8;
        int brow = n_base + ((lane >> 4) & 1) * 8 + (lane & 7);
        int bcol8 = ((lane >> 3) & 1) * 8;
#pragma unroll
        for (int k = 0; k < 256; k += 16) {
            uint32_t afrag[2][4];
#pragma unroll
            for (int mt = 0; mt < 2; mt++)
                ldsm_x4(sa_u + (arow + mt * 16) * SSTRIDE + (k + acol8) * 2, afrag[mt]);
#pragma unroll
            for (int np = 0; np < 4; np++) {
                uint32_t bfrag[4];
                ldsm_x4(sw_u + (brow + np * 16) * SSTRIDE + (k + bcol8) * 2, bfrag);
#pragma unroll
                for (int mt = 0; mt < 2; mt++) {
                    mma_bf16(acc[mt][np * 2],     afrag[mt], bfrag);
                    mma_bf16(acc[mt][np * 2 + 1], afrag[mt], bfrag + 2);
                }
            }
        }
    }
    __syncthreads();

    {
        int n_base = wn * 64;
#pragma unroll
        for (int mt = 0; mt < 2; mt++) {
#pragma unroll
            for (int nt = 0; nt < 8; nt++) {
                int row = m_base + mt * 16 + g;
                int col = n_base + nt * 8 + tig * 2;
                float b0 = fb1s[col], b1 = fb1s[col + 1];
                float t0 = celu3f(acc[mt][nt][0] + b0);
                float t1 = celu3f(acc[mt][nt][1] + b1);
                float t2 = celu3f(acc[mt][nt][2] + b0);
                float t3 = celu3f(acc[mt][nt][3] + b1);
                __nv_bfloat162 p01 = __floats2bfloat162_rn(t0, t1);
                __nv_bfloat162 p23 = __floats2bfloat162_rn(t2, t3);
                *reinterpret_cast<uint32_t*>(sa + row * SSTRIDE + col * 2) =
                    *reinterpret_cast<uint32_t*>(&p01);
                *reinterpret_cast<uint32_t*>(sa + (row + 8) * SSTRIDE + col * 2) =
                    *reinterpret_cast<uint32_t*>(&p23);
            }
        }
    }
    for (int idx = tid; idx < 4096; idx += 512) {
        int r = idx >> 5, c = idx & 31;
        uint4 v = *reinterpret_cast<const uint4*>(g_fw2b + r * 256 + c * 8);
        *reinterpret_cast<uint4*>(sw + r * SSTRIDE + c * 16) = v;
    }
    __syncthreads();

    float acc2[2][4][4];
#pragma unroll
    for (int mt = 0; mt < 2; mt++)
#pragma unroll
        for (int nt = 0; nt < 4; nt++)
#pragma unroll
            for (int c = 0; c < 4; c++) acc2[mt][nt][c] = 0.f;

    {
        int n_base = wn * 32;
        int arow = m_base + (lane & 15);
        int acol8 = ((lane >> 4) & 1) * 8;
        int brow = n_base + ((lane >> 4) & 1) * 8 + (lane & 7);
        int bcol8 = ((lane >> 3) & 1) * 8;
#pragma unroll
        for (int k = 0; k < 256; k += 16) {
            uint32_t afrag[2][4];
#pragma unroll
            for (int mt = 0; mt < 2; mt++)
                ldsm_x4(sa_u + (arow + mt * 16) * SSTRIDE + (k + acol8) * 2, afrag[mt]);
#pragma unroll
            for (int np = 0; np < 2; np++) {
                uint32_t bfrag[4];
                ldsm_x4(sw_u + (brow + np * 16) * SSTRIDE + (k + bcol8) * 2, bfrag);
#pragma unroll
                for (int mt = 0; mt < 2; mt++) {
                    mma_bf16(acc2[mt][np * 2],     afrag[mt], bfrag);
                    mma_bf16(acc2[mt][np * 2 + 1], afrag[mt], bfrag + 2);
                }
            }
        }
    }

    {
        int n_base = wn * 32;
        float ws0 = 0.f, ws1 = 0.f;
        int p = g & 1;
#pragma unroll
        for (int mt = 0; mt < 2; mt++) {
            int row0 = rowbase + m_base + mt * 16 + g;
            int row1 = row0 + 8;
            float s = 0.f;
#pragma unroll
            for (int nt = 0; nt < 4; nt++) {
                int col = n_base + nt * 8 + tig * 2;
                float b0 = fb2s[col], b1 = fb2s[col + 1];
                float w0 = fw3s[col], w1 = fw3s[col + 1];
                float sA = celu3f(acc2[mt][nt][0] + b0) * w0 + celu3f(acc2[mt][nt][1] + b1) * w1;
                float sB = celu3f(acc2[mt][nt][2] + b0) * w0 + celu3f(acc2[mt][nt][3] + b1) * w1;
                if (row0 < ROWS_TOT) s += sA;
                if (row1 < ROWS_TOT) s += sB;
            }
            if (p) ws1 += s; else ws0 += s;
        }
        ws0 = wredsum(ws0);
        ws1 = wredsum(ws1);
        if (lane == 0) { red[wid * 2] = ws0; red[wid * 2 + 1] = ws1; }
    }
    __syncthreads();
    if (tid == 0) {
        float s0 = 0.f, s1 = 0.f;
#pragma unroll
        for (int w = 0; w < 16; w++) { s0 += red[w * 2]; s1 += red[w * 2 + 1]; }
        atomicAdd(&g_w[0], s0);
        atomicAdd(&g_w[1], s1);
    }
}

__global__ void beta_kernel() {
    float w0 = g_w[0] * (1.f / (float)NN);
    float w1 = g_w[1] * (1.f / (float)NN);
    float mx = fmaxf(w0, w1);
    float e0 = expf(w0 - mx), e1 = expf(w1 - mx);
    float inv = 1.f / (e0 + e1);
    g_beta[0] = e0 * inv;
    g_beta[1] = e1 * inv;
}

__global__ void final_kernel(float* __restrict__ out) {
    int idx = blockIdx.x * blockDim.x + threadIdx.x;
    if (idx >= NN * 64) return;
    int n = idx >> 6;
    int q = idx & 63;
    float4 z0 = reinterpret_cast<const float4*>(g_z)[(size_t)n * 128 + q];
    float4 z1 = reinterpret_cast<const float4*>(g_z)[(size_t)n * 128 + 64 + q];
    float b0 = g_beta[0], b1 = g_beta[1];
    float4 o;
    o.x = b0 * z0.x + b1 * z1.x;
    o.y = b0 * z0.y + b1 * z1.y;
    o.z = b0 * z0.z + b1 * z1.z;
    o.w = b0 * z0.w + b1 * z1.w;
    reinterpret_cast<float4*>(out)[idx] = o;
}

// ---------------- launch ----------------
extern "C" void kernel_launch(void* const* d_in, const int* in_sizes, int n_in,
                              void* d_out, int out_size) {
    const float* feat    = (const float*)d_in[0];
    const float* r_vec   = (const float*)d_in[1];
    const float* attn1_w = (const float*)d_in[2];
    const float* attn2   = (const float*)d_in[3];
    const float* fw1     = (const float*)d_in[4];
    const float* fb1     = (const float*)d_in[5];
    const float* fw2     = (const float*)d_in[6];
    const float* fb2     = (const float*)d_in[7];
    const float* fw3     = (const float*)d_in[8];
    const int*   inst    = (const int*)d_in[9];
    float* out = (float*)d_out;

    void* cptr = nullptr;
    cudaGetSymbolAddress(&cptr, g_counts);

    const int SCAN_BLOCKS = (TOT_N + 1023) / 1024; // 98

    init_kernel<<<1, 64>>>(r_vec);
    wconv_kernel<<<(256 * 256 + 255) / 256, 256>>>(fw1, fw2);
    a1n_kernel<<<(NN * 32 + 255) / 256, 256>>>(feat, attn1_w);

    cudaMemsetAsync(cptr, 0, TOT_N * sizeof(int));
    count_kernel<<<(TOT_E + 255) / 256, 256>>>(inst);
    scan1_kernel<<<SCAN_BLOCKS, 1024>>>();
    scan2_kernel<<<1, 1>>>(SCAN_BLOCKS);
    scan3_kernel<<<SCAN_BLOCKS, 1024>>>();
    scatter_kernel<<<(TOT_E + 255) / 256, 256>>>(inst);
    node_fused_kernel<<<(TOT_N * 32 + 255) / 256, 256>>>(feat, attn2);

    cudaFuncSetAttribute(mlp_mma_kernel, cudaFuncAttributeMaxDynamicSharedMemorySize, SMEM_MLP);
    mlp_mma_kernel<<<MLP_CTAS, 512, SMEM_MLP>>>(fb1, fb2, fw3);
    beta_kernel<<<1, 1>>>();
    final_kernel<<<(NN * 64 + 255) / 256, 256>>>(out);
}

// round 9
// speedup vs baseline: 3.0983x; 1.0149x over previous
#include <cuda_runtime.h>
#include <cuda_bf16.h>
#include <math.h>
#include <float.h>
#include <stdint.h>

// Problem constants (fixed by dataset)
#define NN 50000
#define HH 64
#define EE 250000
#define HEADS 4
#define TOT_E (2 * EE)             // edges across both paths
#define TOT_N (2 * NN)             // segments across both paths
#define ROWS_TOT (NN * 2)          // 100000 MLP rows (N nodes x 2 paths)
#define SCAN_BLOCKS ((TOT_N + 1023) / 1024)   // 98

// ---------------- scratch (static device memory; no allocs) ----------------
__device__ float g_fr[2][3][32][2];
__device__ float g_a1n[NN * 4];
__device__ int   g_counts[TOT_N];
__device__ int   g_offsets[TOT_N];
__device__ int   g_cursor[TOT_N];
__device__ int   g_part[128];
__device__ __align__(16) int4 g_einst[TOT_E];  // CSR-sorted (n0,n1,n2,_) per edge
__device__ float g_z[(size_t)NN * 512];                       // fp32 (N, 2, 256)
__device__ __align__(16) __nv_bfloat16 g_zb[(size_t)ROWS_TOT * 256]; // bf16 rows
__device__ __align__(16) __nv_bfloat16 g_fw1b[256 * 256];
__device__ __align__(16) __nv_bfloat16 g_fw2b[128 * 256];
__device__ float g_w[2];

// ---------------- helpers ----------------
__device__ __forceinline__ float celu3f(float x) {
    return x > 0.f ? x : 3.f * (__expf(x * (1.f / 3.f)) - 1.f);
}
__device__ __forceinline__ float sigmf(float x) {
    return __fdividef(1.f, 1.f + __expf(-x));
}
__device__ __forceinline__ float gatef(float x) {
    float se = celu3f(x) * sigmf(x);
    return celu3f(se);
}
__device__ __forceinline__ float wredsum(float v) {
#pragma unroll
    for (int o = 16; o; o >>= 1) v += __shfl_xor_sync(0xffffffffu, v, o);
    return v;
}
__device__ __forceinline__ uint32_t smem_to_u32(const void* p) {
    uint32_t a;
    asm("{ .reg .u64 t; cvta.to.shared.u64 t, %1; cvt.u32.u64 %0, t; }" : "=r"(a) : "l"(p));
    return a;
}

// ldmatrix x4 (four 8x8 b16 tiles)
__device__ __forceinline__ void ldsm_x4(uint32_t addr, uint32_t* r) {
    asm volatile("ldmatrix.sync.aligned.m8n8.x4.shared.b16 {%0,%1,%2,%3}, [%4];"
                 : "=r"(r[0]), "=r"(r[1]), "=r"(r[2]), "=r"(r[3]) : "r"(addr));
}
// mma m16n8k16 bf16 -> f32 accum (in place)
__device__ __forceinline__ void mma_bf16(float* d, const uint32_t* a, const uint32_t* b) {
    asm volatile(
        "mma.sync.aligned.m16n8k16.row.col.f32.bf16.bf16.f32 "
        "{%0,%1,%2,%3}, {%4,%5,%6,%7}, {%8,%9}, {%0,%1,%2,%3};"
        : "+f"(d[0]), "+f"(d[1]), "+f"(d[2]), "+f"(d[3])
        : "r"(a[0]), "r"(a[1]), "r"(a[2]), "r"(a[3]), "r"(b[0]), "r"(b[1]));
}

// ---------------- fused prep kernel (init + wconv + a1n + count) ----------------
// block 0                 : rotation factors + g_w zero
// blocks [1, 257)         : fw1/fw2 -> bf16
// blocks [257, 6507)      : a1n (8 warps/block, one node per warp)
// blocks [6507, 8461)     : segment count histogram
#define PREP_WCONV_B 1
#define PREP_A1N_B   257
#define PREP_CNT_B   6507
#define PREP_GRID    8461

__global__ void prep_kernel(const float* __restrict__ feat, const float* __restrict__ r_vec,
                            const float* __restrict__ aw,
                            const float* __restrict__ fw1, const float* __restrict__ fw2,
                            const int* __restrict__ inst) {
    int b = blockIdx.x;
    int tid = threadIdx.x;
    if (b == 0) {
        if (tid < 2) g_w[tid] = 0.f;
        if (tid < 32) {
            int t = tid;
            float nre[4], nim[4];
#pragma unroll
            for (int r = 0; r < 4; r++) {
                float re = r_vec[r * 64 + t * 2];
                float im = r_vec[r * 64 + t * 2 + 1];
                float inv = rsqrtf(re * re + im * im);
                nre[r] = re * inv;
                nim[r] = im * inv;
            }
#pragma unroll
            for (int m = 0; m < 2; m++) {
                int a = 2 * m + 1, c = 2 * m;
                g_fr[m][2][t][0] = 1.f; g_fr[m][2][t][1] = 0.f;
                g_fr[m][1][t][0] = nre[a]; g_fr[m][1][t][1] = nim[a];
                g_fr[m][0][t][0] = nre[a] * nre[c] - nim[a] * nim[c];
                g_fr[m][0][t][1] = nre[a] * nim[c] + nim[a] * nre[c];
            }
        }
    } else if (b < PREP_A1N_B) {
        int i = (b - PREP_WCONV_B) * 256 + tid;
        if (i < 256 * 256) g_fw1b[i] = __float2bfloat16(fw1[i]);
        if (i < 128 * 256) g_fw2b[i] = __float2bfloat16(fw2[i]);
    } else if (b < PREP_CNT_B) {
        int gw = (b - PREP_A1N_B) * 8 + (tid >> 5);
        int lane = tid & 31;
        if (gw < NN) {
            float2 d = reinterpret_cast<const float2*>(feat)[gw * 32 + lane];
            float p[4];
#pragma unroll
            for (int h = 0; h < 4; h++) {
                float v = aw[h * 64 + 2 * lane] * d.x + aw[h * 64 + 2 * lane + 1] * d.y;
                p[h] = wredsum(v);
            }
            if (lane == 0) {
                float4 r;
                r.x = celu3f(p[0]); r.y = celu3f(p[1]); r.z = celu3f(p[2]); r.w = celu3f(p[3]);
                reinterpret_cast<float4*>(g_a1n)[gw] = r;
            }
        }
    } else {
        int idx = (b - PREP_CNT_B) * 256 + tid;
        if (idx < TOT_E) {
            int m = idx >= EE;
            int e = idx - m * EE;
            int seg = inst[(size_t)m * EE * 3 + (size_t)e * 3];
            atomicAdd(&g_counts[m * NN + seg], 1);
        }
    }
}

// ---------------- scan ----------------
__global__ void scan1_kernel() {
    __shared__ int s[1024];
    int t = threadIdx.x;
    int i = blockIdx.x * 1024 + t;
    int v = (i < TOT_N) ? g_counts[i] : 0;
    s[t] = v;
    __syncthreads();
    for (int off = 1; off < 1024; off <<= 1) {
        int x = (t >= off) ? s[t - off] : 0;
        __syncthreads();
        s[t] += x;
        __syncthreads();
    }
    if (i < TOT_N) g_offsets[i] = s[t] - v;
    if (t == 1023) g_part[blockIdx.x] = s[1023];
}

// Warp-parallel exclusive scan of the 98 block partials (replaces serial 1-thread loop).
__global__ void scan2_kernel() {
    int lane = threadIdx.x;
    int carry = 0;
#pragma unroll
    for (int c = 0; c < 4; c++) {
        int i = c * 32 + lane;
        int v = (i < SCAN_BLOCKS) ? g_part[i] : 0;
        int orig = v;
#pragma unroll
        for (int o = 1; o < 32; o <<= 1) {
            int x = __shfl_up_sync(0xffffffffu, v, o);
            if (lane >= o) v += x;
        }
        int tot = __shfl_sync(0xffffffffu, v, 31);
        if (i < SCAN_BLOCKS) g_part[i] = carry + v - orig;
        carry += tot;
    }
}

__global__ void scan3_kernel() {
    int i = blockIdx.x * 1024 + threadIdx.x;
    if (i < TOT_N) {
        int o = g_offsets[i] + g_part[blockIdx.x];
        g_offsets[i] = o;
        g_cursor[i] = o;
    }
}

// Scatter node-id triplets into CSR order (one int4 per edge).
__global__ void scatter_kernel(const int* __restrict__ inst) {
    int idx = blockIdx.x * blockDim.x + threadIdx.x;
    if (idx >= TOT_E) return;
    int m = idx >= EE;
    int e = idx - m * EE;
    const int* ip = inst + (size_t)m * EE * 3 + (size_t)e * 3;
    int i0 = ip[0], i1 = ip[1], i2 = ip[2];
    int pos = atomicAdd(&g_cursor[m * NN + i0], 1);
    g_einst[pos] = make_int4(i0, i1, i2, 0);
}

// FUSED node kernel: one warp per (path, node); 2x 16-lane subgroups.
__global__ __launch_bounds__(256) void node_fused_kernel(
    const float* __restrict__ feat, const float* __restrict__ attn2) {
    int gw = (blockIdx.x * blockDim.x + threadIdx.x) >> 5;
    int lane = threadIdx.x & 31;
    if (gw >= TOT_N) return;
    int m = gw >= NN;
    int n = gw - m * NN;
    int deg = g_counts[gw];
    int start = g_offsets[gw];
    int sub = lane >> 4;
    int li = lane & 15;

    float2 fr0[3], fr1[3];
#pragma unroll
    for (int p = 0; p < 3; p++) {
        fr0[p] = *reinterpret_cast<const float2*>(&g_fr[m][p][2 * li][0]);
        fr1[p] = *reinterpret_cast<const float2*>(&g_fr[m][p][2 * li + 1][0]);
    }
    float4 at2[4];
#pragma unroll
    for (int h = 0; h < 4; h++)
        at2[h] = *reinterpret_cast<const float4*>(attn2 + h * 64 + 4 * li);
    float4 a1q = *reinterpret_cast<const float4*>(g_a1n + n * 4);
    float a1a[4] = {a1q.x, a1q.y, a1q.z, a1q.w};

    float acc[4][4];
    float den[4] = {0.f, 0.f, 0.f, 0.f};
#pragma unroll
    for (int h = 0; h < 4; h++)
#pragma unroll
        for (int j = 0; j < 4; j++) acc[h][j] = 0.f;

    int padded = (deg + 1) & ~1;
    for (int i = sub; i < padded; i += 2) {
        bool act = i < deg;
        int4 nd = g_einst[start + (act ? i : 0)];
        float mre0 = 0.f, mim0 = 0.f, mre1 = 0.f, mim1 = 0.f;
#pragma unroll
        for (int p = 0; p < 3; p++) {
            int np = (p == 0) ? nd.x : (p == 1) ? nd.y : nd.z;
            float4 d = *reinterpret_cast<const float4*>(feat + (size_t)np * 64 + 4 * li);
            mre0 += d.x * fr0[p].x - d.y * fr0[p].y;
            mim0 += d.x * fr0[p].y + d.y * fr0[p].x;
            mre1 += d.z * fr1[p].x - d.w * fr1[p].y;
            mim1 += d.z * fr1[p].y + d.w * fr1[p].x;
        }
        float ef[4];
        ef[0] = gatef(mre0 * (1.f / 3.f));
        ef[1] = gatef(mim0 * (1.f / 3.f));
        ef[2] = gatef(mre1 * (1.f / 3.f));
        ef[3] = gatef(mim1 * (1.f / 3.f));
        float ph[4];
#pragma unroll
        for (int h = 0; h < 4; h++) {
            ph[h] = at2[h].x * ef[0] + at2[h].y * ef[1]
                  + at2[h].z * ef[2] + at2[h].w * ef[3];
#pragma unroll
            for (int o = 8; o; o >>= 1) ph[h] += __shfl_xor_sync(0xffffffffu, ph[h], o);
        }
#pragma unroll
        for (int h = 0; h < 4; h++) {
            float a = celu3f(a1a[h] + ph[h]);
            float wv = act ? __expf(a) : 0.f;
            den[h] += wv;
            acc[h][0] += wv * ef[0];
            acc[h][1] += wv * ef[1];
            acc[h][2] += wv * ef[2];
            acc[h][3] += wv * ef[3];
        }
    }
#pragma unroll
    for (int h = 0; h < 4; h++) {
        den[h] += __shfl_xor_sync(0xffffffffu, den[h], 16);
#pragma unroll
        for (int j = 0; j < 4; j++)
            acc[h][j] += __shfl_xor_sync(0xffffffffu, acc[h][j], 16);
    }
    if (sub == 0) {
        float* zr = g_z + (size_t)n * 512 + m * 256;
        __nv_bfloat16* zb = g_zb + ((size_t)n * 2 + m) * 256;
#pragma unroll
        for (int h = 0; h < 4; h++) {
            float inv = (deg > 0) ? __fdividef(1.f, den[h]) : 0.f;
            float z0 = celu3f(acc[h][0] * inv);
            float z1 = celu3f(acc[h][1] * inv);
            float z2 = celu3f(acc[h][2] * inv);
            float z3 = celu3f(acc[h][3] * inv);
            *reinterpret_cast<float4*>(zr + h * 64 + 4 * li) = make_float4(z0, z1, z2, z3);
            __nv_bfloat162 b01 = __floats2bfloat162_rn(z0, z1);
            __nv_bfloat162 b23 = __floats2bfloat162_rn(z2, z3);
            *reinterpret_cast<uint32_t*>(zb + h * 64 + 4 * li) =
                *reinterpret_cast<uint32_t*>(&b01);
            *reinterpret_cast<uint32_t*>(zb + h * 64 + 4 * li + 2) =
                *reinterpret_cast<uint32_t*>(&b23);
        }
    }
}

// ---------------- persistent-weight tensor-core MLP ----------------
// 148 CTAs x 512 threads (16 warps: wm=wid>>3 in {0,1}, wn=wid&7).
// Weights W1 (256x264 bf16), W2 (128x264) + biases resident in SMEM for the
// whole kernel; grid-stride loop over 3125 tiles of 32 rows.
#define P_SSTRIDE 528
#define P_OFF_W2  135168
#define P_OFF_A   202752
#define P_OFF_FB1 219648
#define P_OFF_FB2 220672
#define P_OFF_FW3 221184
#define P_OFF_RED 221696
#define P_SMEM    221824
#define MLP_GRID  148
#define N_TILES   ((ROWS_TOT + 31) / 32)     // 3125

__global__ __launch_bounds__(512, 1) void mlp_persist_kernel(
    const float* __restrict__ fb1, const float* __restrict__ fb2,
    const float* __restrict__ fw3) {
    extern __shared__ char smem[];
    char* sw1 = smem;
    char* sw2 = smem + P_OFF_W2;
    char* sa  = smem + P_OFF_A;
    float* fb1s = reinterpret_cast<float*>(smem + P_OFF_FB1);
    float* fb2s = reinterpret_cast<float*>(smem + P_OFF_FB2);
    float* fw3s = reinterpret_cast<float*>(smem + P_OFF_FW3);
    float* red  = reinterpret_cast<float*>(smem + P_OFF_RED);

    uint32_t sw1_u = smem_to_u32(smem);
    uint32_t sw2_u = sw1_u + P_OFF_W2;
    uint32_t sa_u  = sw1_u + P_OFF_A;

    int tid = threadIdx.x;
    int wid = tid >> 5;
    int lane = tid & 31;
    int wm = wid >> 3;       // 0/1 -> rows
    int wn = wid & 7;        // 0..7 -> cols
    int m_base = wm * 16;
    int g = lane >> 2;
    int tig = lane & 3;

    // resident weights + biases
    for (int idx = tid; idx < 8192; idx += 512) {
        int r = idx >> 5, c = idx & 31;
        uint4 v = *reinterpret_cast<const uint4*>(g_fw1b + r * 256 + c * 8);
        *reinterpret_cast<uint4*>(sw1 + r * P_SSTRIDE + c * 16) = v;
    }
    for (int idx = tid; idx < 4096; idx += 512) {
        int r = idx >> 5, c = idx & 31;
        uint4 v = *reinterpret_cast<const uint4*>(g_fw2b + r * 256 + c * 8);
        *reinterpret_cast<uint4*>(sw2 + r * P_SSTRIDE + c * 16) = v;
    }
    for (int i = tid; i < 256; i += 512) fb1s[i] = fb1[i];
    for (int i = tid; i < 128; i += 512) { fb2s[i] = fb2[i]; fw3s[i] = fw3[i]; }
    __syncthreads();

    // ldmatrix address components
    int arow  = m_base + (lane & 15);
    int acol8 = ((lane >> 4) & 1) * 8;
    int brow1 = wn * 32 + ((lane >> 4) & 1) * 8 + (lane & 7);
    int brow2 = wn * 16 + ((lane >> 4) & 1) * 8 + (lane & 7);
    int bcol8 = ((lane >> 3) & 1) * 8;

    float ws0 = 0.f, ws1 = 0.f;

    for (int t = blockIdx.x; t < N_TILES; t += MLP_GRID) {
        int rowbase = t * 32;
        // load A tile (32 rows of g_zb, zero-pad)
        for (int idx = tid; idx < 1024; idx += 512) {
            int r = idx >> 5, c = idx & 31;
            int grow = rowbase + r;
            uint4 v = make_uint4(0, 0, 0, 0);
            if (grow < ROWS_TOT)
                v = *reinterpret_cast<const uint4*>(g_zb + (size_t)grow * 256 + c * 8);
            *reinterpret_cast<uint4*>(sa + r * P_SSTRIDE + c * 16) = v;
        }
        __syncthreads();

        // layer 1: C[32x256] = A @ W1^T ; warp tile 16x32
        float acc[4][4];
#pragma unroll
        for (int nt = 0; nt < 4; nt++)
#pragma unroll
            for (int c = 0; c < 4; c++) acc[nt][c] = 0.f;
#pragma unroll
        for (int k = 0; k < 256; k += 16) {
            uint32_t af[4];
            ldsm_x4(sa_u + arow * P_SSTRIDE + (k + acol8) * 2, af);
#pragma unroll
            for (int np = 0; np < 2; np++) {
                uint32_t bf[4];
                ldsm_x4(sw1_u + (brow1 + np * 16) * P_SSTRIDE + (k + bcol8) * 2, bf);
                mma_bf16(acc[np * 2],     af, bf);
                mma_bf16(acc[np * 2 + 1], af, bf + 2);
            }
        }
        __syncthreads();   // all warps done reading A

        // epilogue 1: t1 = celu3(C + fb1) -> bf16 back into A region
#pragma unroll
        for (int nt = 0; nt < 4; nt++) {
            int row = m_base + g;
            int col = wn * 32 + nt * 8 + tig * 2;
            float b0 = fb1s[col], b1 = fb1s[col + 1];
            float t0 = celu3f(acc[nt][0] + b0);
            float t1 = celu3f(acc[nt][1] + b1);
            float t2 = celu3f(acc[nt][2] + b0);
            float t3 = celu3f(acc[nt][3] + b1);
            __nv_bfloat162 p01 = __floats2bfloat162_rn(t0, t1);
            __nv_bfloat162 p23 = __floats2bfloat162_rn(t2, t3);
            *reinterpret_cast<uint32_t*>(sa + row * P_SSTRIDE + col * 2) =
                *reinterpret_cast<uint32_t*>(&p01);
            *reinterpret_cast<uint32_t*>(sa + (row + 8) * P_SSTRIDE + col * 2) =
                *reinterpret_cast<uint32_t*>(&p23);
        }
        __syncthreads();

        // layer 2: C2[32x128] = t1 @ W2^T ; warp tile 16x16
        float acc2[2][4];
#pragma unroll
        for (int nt = 0; nt < 2; nt++)
#pragma unroll
            for (int c = 0; c < 4; c++) acc2[nt][c] = 0.f;
#pragma unroll
        for (int k = 0; k < 256; k += 16) {
            uint32_t af[4];
            ldsm_x4(sa_u + arow * P_SSTRIDE + (k + acol8) * 2, af);
            uint32_t bf[4];
            ldsm_x4(sw2_u + brow2 * P_SSTRIDE + (k + bcol8) * 2, bf);
            mma_bf16(acc2[0], af, bf);
            mma_bf16(acc2[1], af, bf + 2);
        }

        // epilogue 2: per-row w contribution, split by path parity (row&1)
        {
            int row0 = rowbase + m_base + g;
            int row1 = row0 + 8;
            float sA = 0.f, sB = 0.f;
#pragma unroll
            for (int nt = 0; nt < 2; nt++) {
                int col = wn * 16 + nt * 8 + tig * 2;
                float b0 = fb2s[col], b1 = fb2s[col + 1];
                float w0 = fw3s[col], w1 = fw3s[col + 1];
                sA += celu3f(acc2[nt][0] + b0) * w0 + celu3f(acc2[nt][1] + b1) * w1;
                sB += celu3f(acc2[nt][2] + b0) * w0 + celu3f(acc2[nt][3] + b1) * w1;
            }
            int p = g & 1;   // both row0 and row1 share parity g&1
            float s = 0.f;
            if (row0 < ROWS_TOT) s += sA;
            if (row1 < ROWS_TOT) s += sB;
            if (p) ws1 += s; else ws0 += s;
        }
        __syncthreads();   // protect A region before next tile load
    }

    ws0 = wredsum(ws0);
    ws1 = wredsum(ws1);
    if (lane == 0) { red[wid * 2] = ws0; red[wid * 2 + 1] = ws1; }
    __syncthreads();
    if (tid == 0) {
        float s0 = 0.f, s1 = 0.f;
#pragma unroll
        for (int w = 0; w < 16; w++) { s0 += red[w * 2]; s1 += red[w * 2 + 1]; }
        atomicAdd(&g_w[0], s0);
        atomicAdd(&g_w[1], s1);
    }
}

// final blend; beta computed per block from g_w (kills beta_kernel launch)
__global__ void final_kernel(float* __restrict__ out) {
    __shared__ float bb[2];
    if (threadIdx.x == 0) {
        float w0 = g_w[0] * (1.f / (float)NN);
        float w1 = g_w[1] * (1.f / (float)NN);
        float mx = fmaxf(w0, w1);
        float e0 = expf(w0 - mx), e1 = expf(w1 - mx);
        float inv = 1.f / (e0 + e1);
        bb[0] = e0 * inv;
        bb[1] = e1 * inv;
    }
    __syncthreads();
    int idx = blockIdx.x * blockDim.x + threadIdx.x;
    if (idx >= NN * 64) return;
    int n = idx >> 6;
    int q = idx & 63;
    float4 z0 = reinterpret_cast<const float4*>(g_z)[(size_t)n * 128 + q];
    float4 z1 = reinterpret_cast<const float4*>(g_z)[(size_t)n * 128 + 64 + q];
    float b0 = bb[0], b1 = bb[1];
    float4 o;
    o.x = b0 * z0.x + b1 * z1.x;
    o.y = b0 * z0.y + b1 * z1.y;
    o.z = b0 * z0.z + b1 * z1.z;
    o.w = b0 * z0.w + b1 * z1.w;
    reinterpret_cast<float4*>(out)[idx] = o;
}

// ---------------- launch ----------------
extern "C" void kernel_launch(void* const* d_in, const int* in_sizes, int n_in,
                              void* d_out, int out_size) {
    const float* feat    = (const float*)d_in[0];
    const float* r_vec   = (const float*)d_in[1];
    const float* attn1_w = (const float*)d_in[2];
    const float* attn2   = (const float*)d_in[3];
    const float* fw1     = (const float*)d_in[4];
    const float* fb1     = (const float*)d_in[5];
    const float* fw2     = (const float*)d_in[6];
    const float* fb2     = (const float*)d_in[7];
    const float* fw3     = (const float*)d_in[8];
    const int*   inst    = (const int*)d_in[9];
    float* out = (float*)d_out;

    void* cptr = nullptr;
    cudaGetSymbolAddress(&cptr, g_counts);

    cudaMemsetAsync(cptr, 0, TOT_N * sizeof(int));
    prep_kernel<<<PREP_GRID, 256>>>(feat, r_vec, attn1_w, fw1, fw2, inst);
    scan1_kernel<<<SCAN_BLOCKS, 1024>>>();
    scan2_kernel<<<1, 32>>>();
    scan3_kernel<<<SCAN_BLOCKS, 1024>>>();
    scatter_kernel<<<(TOT_E + 255) / 256, 256>>>(inst);
    node_fused_kernel<<<(TOT_N * 32 + 255) / 256, 256>>>(feat, attn2);

    cudaFuncSetAttribute(mlp_persist_kernel, cudaFuncAttributeMaxDynamicSharedMemorySize, P_SMEM);
    mlp_persist_kernel<<<MLP_GRID, 512, P_SMEM>>>(fb1, fb2, fw3);
    final_kernel<<<(NN * 64 + 255) / 256, 256>>>(out);
}

// round 10
// speedup vs baseline: 3.2053x; 1.0346x over previous
#include <cuda_runtime.h>
#include <cuda_bf16.h>
#include <math.h>
#include <float.h>
#include <stdint.h>

// Problem constants (fixed by dataset)
#define NN 50000
#define HH 64
#define EE 250000
#define HEADS 4
#define TOT_E (2 * EE)             // edges across both paths
#define TOT_N (2 * NN)             // segments across both paths
#define ROWS_TOT (NN * 2)          // 100000 MLP rows (N nodes x 2 paths)
#define SCAN_BLOCKS ((TOT_N + 1023) / 1024)   // 98

// ---------------- scratch (static device memory; no allocs) ----------------
__device__ float g_fr[2][3][32][2];
__device__ float g_a1n[NN * 4];
__device__ int   g_counts[TOT_N];
__device__ int   g_offsets[TOT_N];
__device__ int   g_cursor[TOT_N];
__device__ int   g_part[128];
__device__ __align__(8) int2 g_einst[TOT_E];  // CSR-sorted (n1,n2) per edge (n0 = segment)
__device__ float g_z[(size_t)NN * 512];       // fp32 rows: row (2n+m) x 256
__device__ __align__(16) __nv_bfloat16 g_fw1b[256 * 256];
__device__ __align__(16) __nv_bfloat16 g_fw2b[128 * 256];
__device__ float g_w[2];

// ---------------- helpers ----------------
__device__ __forceinline__ float celu3f(float x) {
    return x > 0.f ? x : 3.f * (__expf(x * (1.f / 3.f)) - 1.f);
}
__device__ __forceinline__ float sigmf(float x) {
    return __fdividef(1.f, 1.f + __expf(-x));
}
__device__ __forceinline__ float gatef(float x) {
    float se = celu3f(x) * sigmf(x);
    return celu3f(se);
}
__device__ __forceinline__ float wredsum(float v) {
#pragma unroll
    for (int o = 16; o; o >>= 1) v += __shfl_xor_sync(0xffffffffu, v, o);
    return v;
}
__device__ __forceinline__ uint32_t smem_to_u32(const void* p) {
    uint32_t a;
    asm("{ .reg .u64 t; cvta.to.shared.u64 t, %1; cvt.u32.u64 %0, t; }" : "=r"(a) : "l"(p));
    return a;
}
__device__ __forceinline__ void ldsm_x4(uint32_t addr, uint32_t* r) {
    asm volatile("ldmatrix.sync.aligned.m8n8.x4.shared.b16 {%0,%1,%2,%3}, [%4];"
                 : "=r"(r[0]), "=r"(r[1]), "=r"(r[2]), "=r"(r[3]) : "r"(addr));
}
__device__ __forceinline__ void mma_bf16(float* d, const uint32_t* a, const uint32_t* b) {
    asm volatile(
        "mma.sync.aligned.m16n8k16.row.col.f32.bf16.bf16.f32 "
        "{%0,%1,%2,%3}, {%4,%5,%6,%7}, {%8,%9}, {%0,%1,%2,%3};"
        : "+f"(d[0]), "+f"(d[1]), "+f"(d[2]), "+f"(d[3])
        : "r"(a[0]), "r"(a[1]), "r"(a[2]), "r"(a[3]), "r"(b[0]), "r"(b[1]));
}
// pack 8 fp32 -> uint4 of bf16x2
__device__ __forceinline__ uint4 pack_bf16x8(float4 a, float4 b) {
    __nv_bfloat162 h0 = __floats2bfloat162_rn(a.x, a.y);
    __nv_bfloat162 h1 = __floats2bfloat162_rn(a.z, a.w);
    __nv_bfloat162 h2 = __floats2bfloat162_rn(b.x, b.y);
    __nv_bfloat162 h3 = __floats2bfloat162_rn(b.z, b.w);
    uint4 u;
    u.x = *reinterpret_cast<uint32_t*>(&h0);
    u.y = *reinterpret_cast<uint32_t*>(&h1);
    u.z = *reinterpret_cast<uint32_t*>(&h2);
    u.w = *reinterpret_cast<uint32_t*>(&h3);
    return u;
}

// ---------------- fused prep kernel (init + wconv + a1n + count) ----------------
#define PREP_WCONV_B 1
#define PREP_A1N_B   257
#define PREP_CNT_B   6507
#define PREP_GRID    8461

__global__ void prep_kernel(const float* __restrict__ feat, const float* __restrict__ r_vec,
                            const float* __restrict__ aw,
                            const float* __restrict__ fw1, const float* __restrict__ fw2,
                            const int* __restrict__ inst) {
    int b = blockIdx.x;
    int tid = threadIdx.x;
    if (b == 0) {
        if (tid < 2) g_w[tid] = 0.f;
        if (tid < 32) {
            int t = tid;
            float nre[4], nim[4];
#pragma unroll
            for (int r = 0; r < 4; r++) {
                float re = r_vec[r * 64 + t * 2];
                float im = r_vec[r * 64 + t * 2 + 1];
                float inv = rsqrtf(re * re + im * im);
                nre[r] = re * inv;
                nim[r] = im * inv;
            }
#pragma unroll
            for (int m = 0; m < 2; m++) {
                int a = 2 * m + 1, c = 2 * m;
                g_fr[m][2][t][0] = 1.f; g_fr[m][2][t][1] = 0.f;
                g_fr[m][1][t][0] = nre[a]; g_fr[m][1][t][1] = nim[a];
                g_fr[m][0][t][0] = nre[a] * nre[c] - nim[a] * nim[c];
                g_fr[m][0][t][1] = nre[a] * nim[c] + nim[a] * nre[c];
            }
        }
    } else if (b < PREP_A1N_B) {
        int i = (b - PREP_WCONV_B) * 256 + tid;
        if (i < 256 * 256) g_fw1b[i] = __float2bfloat16(fw1[i]);
        if (i < 128 * 256) g_fw2b[i] = __float2bfloat16(fw2[i]);
    } else if (b < PREP_CNT_B) {
        int gw = (b - PREP_A1N_B) * 8 + (tid >> 5);
        int lane = tid & 31;
        if (gw < NN) {
            float2 d = reinterpret_cast<const float2*>(feat)[gw * 32 + lane];
            float p[4];
#pragma unroll
            for (int h = 0; h < 4; h++) {
                float v = aw[h * 64 + 2 * lane] * d.x + aw[h * 64 + 2 * lane + 1] * d.y;
                p[h] = wredsum(v);
            }
            if (lane == 0) {
                float4 r;
                r.x = celu3f(p[0]); r.y = celu3f(p[1]); r.z = celu3f(p[2]); r.w = celu3f(p[3]);
                reinterpret_cast<float4*>(g_a1n)[gw] = r;
            }
        }
    } else {
        int idx = (b - PREP_CNT_B) * 256 + tid;
        if (idx < TOT_E) {
            int m = idx >= EE;
            int e = idx - m * EE;
            int seg = inst[(size_t)m * EE * 3 + (size_t)e * 3];
            atomicAdd(&g_counts[m * NN + seg], 1);
        }
    }
}

// ---------------- scan ----------------
__global__ void scan1_kernel() {
    __shared__ int s[1024];
    int t = threadIdx.x;
    int i = blockIdx.x * 1024 + t;
    int v = (i < TOT_N) ? g_counts[i] : 0;
    s[t] = v;
    __syncthreads();
    for (int off = 1; off < 1024; off <<= 1) {
        int x = (t >= off) ? s[t - off] : 0;
        __syncthreads();
        s[t] += x;
        __syncthreads();
    }
    if (i < TOT_N) g_offsets[i] = s[t] - v;
    if (t == 1023) g_part[blockIdx.x] = s[1023];
}

__global__ void scan2_kernel() {
    int lane = threadIdx.x;
    int carry = 0;
#pragma unroll
    for (int c = 0; c < 4; c++) {
        int i = c * 32 + lane;
        int v = (i < SCAN_BLOCKS) ? g_part[i] : 0;
        int orig = v;
#pragma unroll
        for (int o = 1; o < 32; o <<= 1) {
            int x = __shfl_up_sync(0xffffffffu, v, o);
            if (lane >= o) v += x;
        }
        int tot = __shfl_sync(0xffffffffu, v, 31);
        if (i < SCAN_BLOCKS) g_part[i] = carry + v - orig;
        carry += tot;
    }
}

__global__ void scan3_kernel() {
    int i = blockIdx.x * 1024 + threadIdx.x;
    if (i < TOT_N) {
        int o = g_offsets[i] + g_part[blockIdx.x];
        g_offsets[i] = o;
        g_cursor[i] = o;
    }
}

// Scatter (n1,n2) into CSR order (n0 implicit = segment id).
__global__ void scatter_kernel(const int* __restrict__ inst) {
    int idx = blockIdx.x * blockDim.x + threadIdx.x;
    if (idx >= TOT_E) return;
    int m = idx >= EE;
    int e = idx - m * EE;
    const int* ip = inst + (size_t)m * EE * 3 + (size_t)e * 3;
    int i0 = ip[0], i1 = ip[1], i2 = ip[2];
    int pos = atomicAdd(&g_cursor[m * NN + i0], 1);
    g_einst[pos] = make_int2(i1, i2);
}

// FUSED node kernel: one warp per (path, node); 2x 16-lane subgroups.
// n0's feature row + rotation is loop-invariant (CSR) -> hoisted.
__global__ __launch_bounds__(256) void node_fused_kernel(
    const float* __restrict__ feat, const float* __restrict__ attn2) {
    int gw = (blockIdx.x * blockDim.x + threadIdx.x) >> 5;
    int lane = threadIdx.x & 31;
    if (gw >= TOT_N) return;
    int m = gw >= NN;
    int n = gw - m * NN;
    int deg = g_counts[gw];
    int start = g_offsets[gw];
    int sub = lane >> 4;
    int li = lane & 15;

    float2 fr0[3], fr1[3];
#pragma unroll
    for (int p = 0; p < 3; p++) {
        fr0[p] = *reinterpret_cast<const float2*>(&g_fr[m][p][2 * li][0]);
        fr1[p] = *reinterpret_cast<const float2*>(&g_fr[m][p][2 * li + 1][0]);
    }
    float4 at2[4];
#pragma unroll
    for (int h = 0; h < 4; h++)
        at2[h] = *reinterpret_cast<const float4*>(attn2 + h * 64 + 4 * li);
    float4 a1q = *reinterpret_cast<const float4*>(g_a1n + n * 4);
    float a1a[4] = {a1q.x, a1q.y, a1q.z, a1q.w};

    // hoisted n0 (p=0) contribution — identical to all edges of this segment
    float4 d0 = *reinterpret_cast<const float4*>(feat + (size_t)n * 64 + 4 * li);
    float c_re0 = d0.x * fr0[0].x - d0.y * fr0[0].y;
    float c_im0 = d0.x * fr0[0].y + d0.y * fr0[0].x;
    float c_re1 = d0.z * fr1[0].x - d0.w * fr1[0].y;
    float c_im1 = d0.z * fr1[0].y + d0.w * fr1[0].x;

    float acc[4][4];
    float den[4] = {0.f, 0.f, 0.f, 0.f};
#pragma unroll
    for (int h = 0; h < 4; h++)
#pragma unroll
        for (int j = 0; j < 4; j++) acc[h][j] = 0.f;

    int padded = (deg + 1) & ~1;
    for (int i = sub; i < padded; i += 2) {
        bool act = i < deg;
        int2 nd = g_einst[start + (act ? i : 0)];
        float mre0 = c_re0, mim0 = c_im0, mre1 = c_re1, mim1 = c_im1;
        {
            float4 d = *reinterpret_cast<const float4*>(feat + (size_t)nd.x * 64 + 4 * li);
            mre0 += d.x * fr0[1].x - d.y * fr0[1].y;
            mim0 += d.x * fr0[1].y + d.y * fr0[1].x;
            mre1 += d.z * fr1[1].x - d.w * fr1[1].y;
            mim1 += d.z * fr1[1].y + d.w * fr1[1].x;
        }
        {
            float4 d = *reinterpret_cast<const float4*>(feat + (size_t)nd.y * 64 + 4 * li);
            mre0 += d.x * fr0[2].x - d.y * fr0[2].y;
            mim0 += d.x * fr0[2].y + d.y * fr0[2].x;
            mre1 += d.z * fr1[2].x - d.w * fr1[2].y;
            mim1 += d.z * fr1[2].y + d.w * fr1[2].x;
        }
        float ef[4];
        ef[0] = gatef(mre0 * (1.f / 3.f));
        ef[1] = gatef(mim0 * (1.f / 3.f));
        ef[2] = gatef(mre1 * (1.f / 3.f));
        ef[3] = gatef(mim1 * (1.f / 3.f));
        float ph[4];
#pragma unroll
        for (int h = 0; h < 4; h++) {
            ph[h] = at2[h].x * ef[0] + at2[h].y * ef[1]
                  + at2[h].z * ef[2] + at2[h].w * ef[3];
#pragma unroll
            for (int o = 8; o; o >>= 1) ph[h] += __shfl_xor_sync(0xffffffffu, ph[h], o);
        }
#pragma unroll
        for (int h = 0; h < 4; h++) {
            float a = celu3f(a1a[h] + ph[h]);
            float wv = act ? __expf(a) : 0.f;
            den[h] += wv;
            acc[h][0] += wv * ef[0];
            acc[h][1] += wv * ef[1];
            acc[h][2] += wv * ef[2];
            acc[h][3] += wv * ef[3];
        }
    }
#pragma unroll
    for (int h = 0; h < 4; h++) {
        den[h] += __shfl_xor_sync(0xffffffffu, den[h], 16);
#pragma unroll
        for (int j = 0; j < 4; j++)
            acc[h][j] += __shfl_xor_sync(0xffffffffu, acc[h][j], 16);
    }
    if (sub == 0) {
        float* zr = g_z + (size_t)n * 512 + m * 256;
#pragma unroll
        for (int h = 0; h < 4; h++) {
            float inv = (deg > 0) ? __fdividef(1.f, den[h]) : 0.f;
            float z0 = celu3f(acc[h][0] * inv);
            float z1 = celu3f(acc[h][1] * inv);
            float z2 = celu3f(acc[h][2] * inv);
            float z3 = celu3f(acc[h][3] * inv);
            *reinterpret_cast<float4*>(zr + h * 64 + 4 * li) = make_float4(z0, z1, z2, z3);
        }
    }
}

// ---------------- persistent-weight tensor-core MLP ----------------
// Weights resident in SMEM; grid-stride over 32-row tiles; A staged from fp32
// g_z with in-register cvt->bf16 and software prefetch of the next tile.
#define P_SSTRIDE 528
#define P_OFF_W2  135168
#define P_OFF_A   202752
#define P_OFF_FB1 219648
#define P_OFF_FB2 220672
#define P_OFF_FW3 221184
#define P_OFF_RED 221696
#define P_SMEM    221824
#define MLP_GRID  148
#define N_TILES   ((ROWS_TOT + 31) / 32)     // 3125

__global__ __launch_bounds__(512, 1) void mlp_persist_kernel(
    const float* __restrict__ fb1, const float* __restrict__ fb2,
    const float* __restrict__ fw3) {
    extern __shared__ char smem[];
    char* sw1 = smem;
    char* sw2 = smem + P_OFF_W2;
    char* sa  = smem + P_OFF_A;
    float* fb1s = reinterpret_cast<float*>(smem + P_OFF_FB1);
    float* fb2s = reinterpret_cast<float*>(smem + P_OFF_FB2);
    float* fw3s = reinterpret_cast<float*>(smem + P_OFF_FW3);
    float* red  = reinterpret_cast<float*>(smem + P_OFF_RED);

    uint32_t sw1_u = smem_to_u32(smem);
    uint32_t sw2_u = sw1_u + P_OFF_W2;
    uint32_t sa_u  = sw1_u + P_OFF_A;

    int tid = threadIdx.x;
    int wid = tid >> 5;
    int lane = tid & 31;
    int wm = wid >> 3;       // 0/1 -> rows
    int wn = wid & 7;        // 0..7 -> cols
    int m_base = wm * 16;
    int g = lane >> 2;
    int tig = lane & 3;

    // resident weights + biases
    for (int idx = tid; idx < 8192; idx += 512) {
        int r = idx >> 5, c = idx & 31;
        uint4 v = *reinterpret_cast<const uint4*>(g_fw1b + r * 256 + c * 8);
        *reinterpret_cast<uint4*>(sw1 + r * P_SSTRIDE + c * 16) = v;
    }
    for (int idx = tid; idx < 4096; idx += 512) {
        int r = idx >> 5, c = idx & 31;
        uint4 v = *reinterpret_cast<const uint4*>(g_fw2b + r * 256 + c * 8);
        *reinterpret_cast<uint4*>(sw2 + r * P_SSTRIDE + c * 16) = v;
    }
    for (int i = tid; i < 256; i += 512) fb1s[i] = fb1[i];
    for (int i = tid; i < 128; i += 512) { fb2s[i] = fb2[i]; fw3s[i] = fw3[i]; }

    // A-chunk mapping: this thread owns chunks tid*2, tid*2+1 (16B bf16 each)
    int r0 = (tid * 2) >> 5,     c0 = (tid * 2) & 31;
    int r1 = (tid * 2 + 1) >> 5, c1 = (tid * 2 + 1) & 31;

    // stage first tile
    {
        int rowbase = blockIdx.x * 32;
        float4 a0 = make_float4(0, 0, 0, 0), b0 = a0, a1 = a0, b1 = a0;
        if (rowbase + r0 < ROWS_TOT) {
            const float4* zp = reinterpret_cast<const float4*>(g_z + (size_t)(rowbase + r0) * 256 + c0 * 8);
            a0 = zp[0]; b0 = zp[1];
        }
        if (rowbase + r1 < ROWS_TOT) {
            const float4* zp = reinterpret_cast<const float4*>(g_z + (size_t)(rowbase + r1) * 256 + c1 * 8);
            a1 = zp[0]; b1 = zp[1];
        }
        *reinterpret_cast<uint4*>(sa + r0 * P_SSTRIDE + c0 * 16) = pack_bf16x8(a0, b0);
        *reinterpret_cast<uint4*>(sa + r1 * P_SSTRIDE + c1 * 16) = pack_bf16x8(a1, b1);
    }
    __syncthreads();

    int arow  = m_base + (lane & 15);
    int acol8 = ((lane >> 4) & 1) * 8;
    int brow1 = wn * 32 + ((lane >> 4) & 1) * 8 + (lane & 7);
    int brow2 = wn * 16 + ((lane >> 4) & 1) * 8 + (lane & 7);
    int bcol8 = ((lane >> 3) & 1) * 8;

    float ws0 = 0.f, ws1 = 0.f;

    for (int t = blockIdx.x; t < N_TILES; t += MLP_GRID) {
        int rowbase = t * 32;
        int tn = t + MLP_GRID;
        bool has_next = tn < N_TILES;

        // prefetch next tile (fp32) into registers; latency hides under MMAs
        float4 pa0 = make_float4(0, 0, 0, 0), pb0 = pa0, pa1 = pa0, pb1 = pa0;
        if (has_next) {
            int nb = tn * 32;
            if (nb + r0 < ROWS_TOT) {
                const float4* zp = reinterpret_cast<const float4*>(g_z + (size_t)(nb + r0) * 256 + c0 * 8);
                pa0 = zp[0]; pb0 = zp[1];
            }
            if (nb + r1 < ROWS_TOT) {
                const float4* zp = reinterpret_cast<const float4*>(g_z + (size_t)(nb + r1) * 256 + c1 * 8);
                pa1 = zp[0]; pb1 = zp[1];
            }
        }

        // layer 1: C[32x256] = A @ W1^T ; warp tile 16x32
        float acc[4][4];
#pragma unroll
        for (int nt = 0; nt < 4; nt++)
#pragma unroll
            for (int c = 0; c < 4; c++) acc[nt][c] = 0.f;
#pragma unroll
        for (int k = 0; k < 256; k += 16) {
            uint32_t af[4];
            ldsm_x4(sa_u + arow * P_SSTRIDE + (k + acol8) * 2, af);
#pragma unroll
            for (int np = 0; np < 2; np++) {
                uint32_t bf[4];
                ldsm_x4(sw1_u + (brow1 + np * 16) * P_SSTRIDE + (k + bcol8) * 2, bf);
                mma_bf16(acc[np * 2],     af, bf);
                mma_bf16(acc[np * 2 + 1], af, bf + 2);
            }
        }
        __syncthreads();

        // epilogue 1: t1 = celu3(C + fb1) -> bf16 back into A region
#pragma unroll
        for (int nt = 0; nt < 4; nt++) {
            int row = m_base + g;
            int col = wn * 32 + nt * 8 + tig * 2;
            float b0 = fb1s[col], b1 = fb1s[col + 1];
            float t0 = celu3f(acc[nt][0] + b0);
            float t1 = celu3f(acc[nt][1] + b1);
            float t2 = celu3f(acc[nt][2] + b0);
            float t3 = celu3f(acc[nt][3] + b1);
            __nv_bfloat162 p01 = __floats2bfloat162_rn(t0, t1);
            __nv_bfloat162 p23 = __floats2bfloat162_rn(t2, t3);
            *reinterpret_cast<uint32_t*>(sa + row * P_SSTRIDE + col * 2) =
                *reinterpret_cast<uint32_t*>(&p01);
            *reinterpret_cast<uint32_t*>(sa + (row + 8) * P_SSTRIDE + col * 2) =
                *reinterpret_cast<uint32_t*>(&p23);
        }
        __syncthreads();

        // layer 2: C2[32x128] = t1 @ W2^T ; warp tile 16x16
        float acc2[2][4];
#pragma unroll
        for (int nt = 0; nt < 2; nt++)
#pragma unroll
            for (int c = 0; c < 4; c++) acc2[nt][c] = 0.f;
#pragma unroll
        for (int k = 0; k < 256; k += 16) {
            uint32_t af[4];
            ldsm_x4(sa_u + arow * P_SSTRIDE + (k + acol8) * 2, af);
            uint32_t bf[4];
            ldsm_x4(sw2_u + brow2 * P_SSTRIDE + (k + bcol8) * 2, bf);
            mma_bf16(acc2[0], af, bf);
            mma_bf16(acc2[1], af, bf + 2);
        }

        // epilogue 2: per-row w contribution, split by path parity (row&1)
        {
            int row0 = rowbase + m_base + g;
            int row1 = row0 + 8;
            float sA = 0.f, sB = 0.f;
#pragma unroll
            for (int nt = 0; nt < 2; nt++) {
                int col = wn * 16 + nt * 8 + tig * 2;
                float b0 = fb2s[col], b1 = fb2s[col + 1];
                float w0 = fw3s[col], w1 = fw3s[col + 1];
                sA += celu3f(acc2[nt][0] + b0) * w0 + celu3f(acc2[nt][1] + b1) * w1;
                sB += celu3f(acc2[nt][2] + b0) * w0 + celu3f(acc2[nt][3] + b1) * w1;
            }
            int p = g & 1;
            float s = 0.f;
            if (row0 < ROWS_TOT) s += sA;
            if (row1 < ROWS_TOT) s += sB;
            if (p) ws1 += s; else ws0 += s;
        }
        __syncthreads();   // everyone done reading t1 from A region

        if (has_next) {
            *reinterpret_cast<uint4*>(sa + r0 * P_SSTRIDE + c0 * 16) = pack_bf16x8(pa0, pb0);
            *reinterpret_cast<uint4*>(sa + r1 * P_SSTRIDE + c1 * 16) = pack_bf16x8(pa1, pb1);
        }
        __syncthreads();
    }

    ws0 = wredsum(ws0);
    ws1 = wredsum(ws1);
    if (lane == 0) { red[wid * 2] = ws0; red[wid * 2 + 1] = ws1; }
    __syncthreads();
    if (tid == 0) {
        float s0 = 0.f, s1 = 0.f;
#pragma unroll
        for (int w = 0; w < 16; w++) { s0 += red[w * 2]; s1 += red[w * 2 + 1]; }
        atomicAdd(&g_w[0], s0);
        atomicAdd(&g_w[1], s1);
    }
}

// final blend; beta computed per block from g_w
__global__ void final_kernel(float* __restrict__ out) {
    __shared__ float bb[2];
    if (threadIdx.x == 0) {
        float w0 = g_w[0] * (1.f / (float)NN);
        float w1 = g_w[1] * (1.f / (float)NN);
        float mx = fmaxf(w0, w1);
        float e0 = expf(w0 - mx), e1 = expf(w1 - mx);
        float inv = 1.f / (e0 + e1);
        bb[0] = e0 * inv;
        bb[1] = e1 * inv;
    }
    __syncthreads();
    int idx = blockIdx.x * blockDim.x + threadIdx.x;
    if (idx >= NN * 64) return;
    int n = idx >> 6;
    int q = idx & 63;
    float4 z0 = reinterpret_cast<const float4*>(g_z)[(size_t)n * 128 + q];
    float4 z1 = reinterpret_cast<const float4*>(g_z)[(size_t)n * 128 + 64 + q];
    float b0 = bb[0], b1 = bb[1];
    float4 o;
    o.x = b0 * z0.x + b1 * z1.x;
    o.y = b0 * z0.y + b1 * z1.y;
    o.z = b0 * z0.z + b1 * z1.z;
    o.w = b0 * z0.w + b1 * z1.w;
    reinterpret_cast<float4*>(out)[idx] = o;
}

// ---------------- launch ----------------
extern "C" void kernel_launch(void* const* d_in, const int* in_sizes, int n_in,
                              void* d_out, int out_size) {
    const float* feat    = (const float*)d_in[0];
    const float* r_vec   = (const float*)d_in[1];
    const float* attn1_w = (const float*)d_in[2];
    const float* attn2   = (const float*)d_in[3];
    const float* fw1     = (const float*)d_in[4];
    const float* fb1     = (const float*)d_in[5];
    const float* fw2     = (const float*)d_in[6];
    const float* fb2     = (const float*)d_in[7];
    const float* fw3     = (const float*)d_in[8];
    const int*   inst    = (const int*)d_in[9];
    float* out = (float*)d_out;

    void* cptr = nullptr;
    cudaGetSymbolAddress(&cptr, g_counts);

    cudaMemsetAsync(cptr, 0, TOT_N * sizeof(int));
    prep_kernel<<<PREP_GRID, 256>>>(feat, r_vec, attn1_w, fw1, fw2, inst);
    scan1_kernel<<<SCAN_BLOCKS, 1024>>>();
    scan2_kernel<<<1, 32>>>();
    scan3_kernel<<<SCAN_BLOCKS, 1024>>>();
    scatter_kernel<<<(TOT_E + 255) / 256, 256>>>(inst);
    node_fused_kernel<<<(TOT_N * 32 + 255) / 256, 256>>>(feat, attn2);

    cudaFuncSetAttribute(mlp_persist_kernel, cudaFuncAttributeMaxDynamicSharedMemorySize, P_SMEM);
    mlp_persist_kernel<<<MLP_GRID, 512, P_SMEM>>>(fb1, fb2, fw3);
    final_kernel<<<(NN * 64 + 255) / 256, 256>>>(out);
}